// round 10
// baseline (speedup 1.0000x reference)
#include <cuda_runtime.h>
#include <cuda_bf16.h>
#include <cstdint>

#define N_NODES  100000
#define N_EDGES  1600000
#define IN_CH    128
#define HID      256
#define OUT_CH   128
#define N_GRAPHS 2048

// ---------------- scratch (device globals: no allocation allowed) ----------------
__device__ int   g_deg[N_NODES];
__device__ int   g_fill[N_NODES];
__device__ int   g_rowptr[N_NODES + 1];
__device__ int   g_col[N_EDGES];
__device__ int   g_part[128];
__device__ int   g_part2[128];
__device__ int   g_gcnt[N_GRAPHS];
__device__ uint16_t g_Ah[(size_t)N_NODES * 512];
__device__ uint16_t g_Al[(size_t)N_NODES * 512];
__device__ uint16_t g_B1h[256 * 512], g_B1l[256 * 512];
__device__ uint16_t g_B2h[256 * 512], g_B2l[256 * 512];
__device__ float g_h1   [(size_t)N_NODES * HID];
__device__ float g_part1[(size_t)N_NODES * HID];   // fp32 partial (self-GEMM output)
__device__ float g_pool  [N_GRAPHS * HID];
__device__ float g_hidden[N_GRAPHS * HID];

// ---------------- helpers ----------------
__device__ __forceinline__ uint16_t bf_hi_bits(float v, float& hf) {
    __nv_bfloat16 b = __float2bfloat16_rn(v);
    hf = __bfloat162float(b);
    return *(uint16_t*)&b;
}
__device__ __forceinline__ uint16_t bf_bits(float v) {
    __nv_bfloat16 b = __float2bfloat16_rn(v);
    return *(uint16_t*)&b;
}
__device__ __forceinline__ uint32_t smem_u32(const void* p) {
    uint32_t a;
    asm("{ .reg .u64 t; cvta.to.shared.u64 t, %1; cvt.u32.u64 %0, t; }" : "=r"(a) : "l"(p));
    return a;
}

// packed f32x2 helpers (head MLP GEMM)
__device__ __forceinline__ void fma2(unsigned long long& c, unsigned long long a, unsigned long long b) {
    asm("fma.rn.f32x2 %0, %1, %2, %3;" : "=l"(c) : "l"(a), "l"(b), "l"(c));
}
__device__ __forceinline__ unsigned long long pk2(float lo, float hi) {
    unsigned long long r; asm("mov.b64 %0, {%1, %2};" : "=l"(r) : "f"(lo), "f"(hi)); return r;
}
__device__ __forceinline__ unsigned long long dup2(float x) {
    unsigned long long r; asm("mov.b64 %0, {%1, %1};" : "=l"(r) : "f"(x)); return r;
}
__device__ __forceinline__ float2 upk2(unsigned long long v) {
    float2 r; asm("mov.b64 {%0, %1}, %2;" : "=f"(r.x), "=f"(r.y) : "l"(v)); return r;
}

// ---------------- CSR build + zero ----------------
__global__ void zero_kernel() {
    int i = blockIdx.x * blockDim.x + threadIdx.x;
    if (i < N_NODES) { g_deg[i] = 0; g_fill[i] = 0; }
    if (i < N_GRAPHS * HID) g_pool[i] = 0.f;
    if (i < N_GRAPHS) g_gcnt[i] = 0;
}
__global__ void hist_kernel(const int* __restrict__ dst, const int* __restrict__ batch) {
    int e = blockIdx.x * blockDim.x + threadIdx.x;
    if (e < N_EDGES) atomicAdd(&g_deg[dst[e]], 1);
    if (e < N_NODES) atomicAdd(&g_gcnt[batch[e]], 1);
}
__global__ void scan1_kernel() {
    __shared__ int sh[1024];
    int t = threadIdx.x;
    int i = blockIdx.x * 1024 + t;
    sh[t] = (i < N_NODES) ? g_deg[i] : 0;
    __syncthreads();
    for (int off = 512; off > 0; off >>= 1) {
        if (t < off) sh[t] += sh[t + off];
        __syncthreads();
    }
    if (t == 0) g_part[blockIdx.x] = sh[0];
}
__global__ void scan2_kernel(int nparts) {
    __shared__ int sh[128];
    int t = threadIdx.x;
    int v = (t < nparts) ? g_part[t] : 0;
    sh[t] = v;
    __syncthreads();
    for (int off = 1; off < 128; off <<= 1) {
        int nv = (t >= off) ? sh[t - off] : 0;
        __syncthreads();
        sh[t] += nv;
        __syncthreads();
    }
    if (t < nparts) g_part2[t] = sh[t] - v;
    if (t == 0) g_rowptr[N_NODES] = N_EDGES;
}
__global__ void scan3_kernel() {
    __shared__ int sh[1024];
    int t = threadIdx.x;
    int i = blockIdx.x * 1024 + t;
    int v = (i < N_NODES) ? g_deg[i] : 0;
    sh[t] = v;
    __syncthreads();
    for (int off = 1; off < 1024; off <<= 1) {
        int nv = (t >= off) ? sh[t - off] : 0;
        __syncthreads();
        sh[t] += nv;
        __syncthreads();
    }
    if (i < N_NODES) g_rowptr[i] = sh[t] - v + g_part2[blockIdx.x];
}
__global__ void scatter_kernel(const int* __restrict__ src, const int* __restrict__ dst) {
    int e = blockIdx.x * blockDim.x + threadIdx.x;
    if (e >= N_EDGES) return;
    int d = dst[e];
    int p = g_rowptr[d] + atomicAdd(&g_fill[d], 1);
    g_col[p] = src[e];
}

// ---------------- split writers ----------------
__device__ __forceinline__ void split_store4(uint16_t* Ah, uint16_t* Al, size_t base,
                                             float v0, float v1, float v2, float v3) {
    float hf0, hf1, hf2, hf3;
    uint16_t h0 = bf_hi_bits(v0, hf0), h1 = bf_hi_bits(v1, hf1);
    uint16_t h2 = bf_hi_bits(v2, hf2), h3 = bf_hi_bits(v3, hf3);
    uint16_t l0 = bf_bits(v0 - hf0), l1 = bf_bits(v1 - hf1);
    uint16_t l2 = bf_bits(v2 - hf2), l3 = bf_bits(v3 - hf3);
    *(uint2*)(Ah + base) = make_uint2((uint32_t)h0 | ((uint32_t)h1 << 16),
                                      (uint32_t)h2 | ((uint32_t)h3 << 16));
    *(uint2*)(Al + base) = make_uint2((uint32_t)l0 | ((uint32_t)l1 << 16),
                                      (uint32_t)l2 | ((uint32_t)l3 << 16));
}

// mean aggregation (one warp per node, 2-way edge unroll) with fused split
template <int C>
__global__ void agg_split_kernel(const float* __restrict__ feat,
                                 uint16_t* __restrict__ Ah, uint16_t* __restrict__ Al) {
    int w = (blockIdx.x * blockDim.x + threadIdx.x) >> 5;
    int lane = threadIdx.x & 31;
    if (w >= N_NODES) return;
    int beg = g_rowptr[w], end = g_rowptr[w + 1];
    constexpr int V = C / 128;
    float4 acc[V];
#pragma unroll
    for (int v = 0; v < V; v++) acc[v] = make_float4(0.f, 0.f, 0.f, 0.f);
    int j = beg;
    for (; j + 1 < end; j += 2) {
        int s0 = g_col[j], s1 = g_col[j + 1];
        const float4* r0 = (const float4*)(feat + (size_t)s0 * C);
        const float4* r1 = (const float4*)(feat + (size_t)s1 * C);
#pragma unroll
        for (int v = 0; v < V; v++) {
            float4 t0 = r0[lane + 32 * v];
            float4 t1 = r1[lane + 32 * v];
            acc[v].x += t0.x; acc[v].y += t0.y; acc[v].z += t0.z; acc[v].w += t0.w;
            acc[v].x += t1.x; acc[v].y += t1.y; acc[v].z += t1.z; acc[v].w += t1.w;
        }
    }
    if (j < end) {
        int s0 = g_col[j];
        const float4* r0 = (const float4*)(feat + (size_t)s0 * C);
#pragma unroll
        for (int v = 0; v < V; v++) {
            float4 t0 = r0[lane + 32 * v];
            acc[v].x += t0.x; acc[v].y += t0.y; acc[v].z += t0.z; acc[v].w += t0.w;
        }
    }
    float inv = (end > beg) ? 1.f / (float)(end - beg) : 0.f;
#pragma unroll
    for (int v = 0; v < V; v++) {
        size_t base = (size_t)w * 512 + (size_t)(lane + 32 * v) * 4;
        split_store4(Ah, Al, base, acc[v].x * inv, acc[v].y * inv, acc[v].z * inv, acc[v].w * inv);
    }
}

// split x (fp32 [N,128]) into A panel cols 128..255
__global__ void xsplit_kernel(const float* __restrict__ x,
                              uint16_t* __restrict__ Ah, uint16_t* __restrict__ Al) {
    int idx = blockIdx.x * blockDim.x + threadIdx.x;
    if (idx >= N_NODES * 32) return;
    int row = idx >> 5, q = idx & 31;
    float4 v = ((const float4*)x)[idx];
    split_store4(Ah, Al, (size_t)row * 512 + 128 + (size_t)q * 4, v.x, v.y, v.z, v.w);
}

// transpose + split weight W[Kw,256] into B panel
__global__ void wsplit_kernel(const float* __restrict__ W, int Kw, int cofs,
                              uint16_t* __restrict__ Bh, uint16_t* __restrict__ Bl) {
    int idx = blockIdx.x * blockDim.x + threadIdx.x;
    if (idx >= 256 * Kw) return;
    int n = idx / Kw, k = idx - n * Kw;
    float v = W[(size_t)k * 256 + n];
    float hf; uint16_t h = bf_hi_bits(v, hf);
    Bh[(size_t)n * 512 + cofs + k] = h;
    Bl[(size_t)n * 512 + cofs + k] = bf_bits(v - hf);
}

// ---------------- pre-split bf16 HMMA GEMM (register prefetch) ----------------
// Modes: store_raw=1  -> Cc[r,c] = raw accum (no bias/relu) — partial pass.
//        fuse_pool=0  -> Cc = relu(acc + bias + Cacc?); optional split store to oAh/oAl.
//        fuse_pool=1  -> segmented pool of relu(acc + bias + Cacc?) into psum.
#define LDB_S 40

__device__ __forceinline__ void mma_bf16(float* c, const uint32_t* a, const uint32_t* b) {
    asm volatile(
        "mma.sync.aligned.m16n8k16.row.col.f32.bf16.bf16.f32 "
        "{%0,%1,%2,%3}, {%4,%5,%6,%7}, {%8,%9}, {%0,%1,%2,%3};"
        : "+f"(c[0]), "+f"(c[1]), "+f"(c[2]), "+f"(c[3])
        : "r"(a[0]), "r"(a[1]), "r"(a[2]), "r"(a[3]), "r"(b[0]), "r"(b[1]));
}
__device__ __forceinline__ void ldsm_x4(uint32_t* r, uint32_t addr) {
    asm volatile("ldmatrix.sync.aligned.m8n8.x4.shared.b16 {%0,%1,%2,%3}, [%4];"
                 : "=r"(r[0]), "=r"(r[1]), "=r"(r[2]), "=r"(r[3]) : "r"(addr));
}

__global__ __launch_bounds__(256, 1) void hgemm_kernel(
    const uint16_t* __restrict__ Ah, const uint16_t* __restrict__ Al,
    const uint16_t* __restrict__ Bh, const uint16_t* __restrict__ Bl,
    int K, const float* __restrict__ bias, float* __restrict__ Cc,
    const float* __restrict__ Cacc,
    uint16_t* __restrict__ oAh, uint16_t* __restrict__ oAl,
    int M, int store_raw,
    const int* __restrict__ batchp, float* __restrict__ psum, int fuse_pool)
{
    __shared__ __align__(16) uint8_t smraw[40960];
    uint16_t* As_h = (uint16_t*)(smraw);
    uint16_t* As_l = (uint16_t*)(smraw + 10240);
    uint16_t* Bs_h = (uint16_t*)(smraw + 20480);
    uint16_t* Bs_l = (uint16_t*)(smraw + 30720);

    const int tid = threadIdx.x;
    const int lane = tid & 31, wid = tid >> 5;
    const int wm = wid & 3, wn = wid >> 2;
    const int g = lane >> 2, th = lane & 3;
    const int row0 = blockIdx.x * 128;
    const int n0 = blockIdx.y * 128;

    const uint32_t sAh = smem_u32(smraw);
    const uint32_t sAl = sAh + 10240;
    const uint32_t sBh = sAh + 20480;
    const uint32_t sBl = sAh + 30720;

    const int nch = K >> 5;

    float acc[2][8][4];
#pragma unroll
    for (int mt = 0; mt < 2; mt++)
#pragma unroll
        for (int nt = 0; nt < 8; nt++)
#pragma unroll
            for (int r = 0; r < 4; r++) acc[mt][nt][r] = 0.f;

    const int lt = lane >> 3, lr = lane & 7;
    const int pr = tid >> 2, pq = tid & 3;

    uint4 ra_h[2], ra_l[2], rb_h[2], rb_l[2];

    {
#pragma unroll
        for (int i = 0; i < 2; i++) {
            int r = pr + i * 64;
            int ga = row0 + r;
            size_t ao = (size_t)ga * 512 + pq * 8;
            if (ga < M) { ra_h[i] = *(const uint4*)(Ah + ao); ra_l[i] = *(const uint4*)(Al + ao); }
            else        { ra_h[i] = make_uint4(0,0,0,0);      ra_l[i] = make_uint4(0,0,0,0); }
            size_t bo = (size_t)(n0 + r) * 512 + pq * 8;
            rb_h[i] = *(const uint4*)(Bh + bo);
            rb_l[i] = *(const uint4*)(Bl + bo);
        }
    }

#pragma unroll 1
    for (int c = 0; c < nch; c++) {
#pragma unroll
        for (int i = 0; i < 2; i++) {
            int r = pr + i * 64;
            int so = r * LDB_S + pq * 8;
            *(uint4*)&As_h[so] = ra_h[i];
            *(uint4*)&As_l[so] = ra_l[i];
            *(uint4*)&Bs_h[so] = rb_h[i];
            *(uint4*)&Bs_l[so] = rb_l[i];
        }
        __syncthreads();

        if (c + 1 < nch) {
            int kb = (c + 1) * 32;
#pragma unroll
            for (int i = 0; i < 2; i++) {
                int r = pr + i * 64;
                int ga = row0 + r;
                size_t ao = (size_t)ga * 512 + kb + pq * 8;
                if (ga < M) { ra_h[i] = *(const uint4*)(Ah + ao); ra_l[i] = *(const uint4*)(Al + ao); }
                else        { ra_h[i] = make_uint4(0,0,0,0);      ra_l[i] = make_uint4(0,0,0,0); }
                size_t bo = (size_t)(n0 + r) * 512 + kb + pq * 8;
                rb_h[i] = *(const uint4*)(Bh + bo);
                rb_l[i] = *(const uint4*)(Bl + bo);
            }
        }

#pragma unroll
        for (int step = 0; step < 2; step++) {
            const int k0 = step * 16;
            uint32_t aoff[2];
#pragma unroll
            for (int mt = 0; mt < 2; mt++) {
                int ar = wm * 32 + mt * 16 + (lt & 1) * 8 + lr;
                int ak = k0 + (lt >> 1) * 8;
                aoff[mt] = (uint32_t)(ar * LDB_S + ak) * 2;
            }
            uint32_t boff[4];
#pragma unroll
            for (int ntp = 0; ntp < 4; ntp++) {
                int nr = wn * 64 + ntp * 16 + (lt >> 1) * 8 + lr;
                int nk = k0 + (lt & 1) * 8;
                boff[ntp] = (uint32_t)(nr * LDB_S + nk) * 2;
            }

            uint32_t ah[2][4], al[2][4], bh[4][4], bl[4][4];
#pragma unroll
            for (int mt = 0; mt < 2; mt++) ldsm_x4(ah[mt], sAh + aoff[mt]);
#pragma unroll
            for (int ntp = 0; ntp < 4; ntp++) ldsm_x4(bh[ntp], sBh + boff[ntp]);
#pragma unroll
            for (int mt = 0; mt < 2; mt++)
#pragma unroll
                for (int nt = 0; nt < 8; nt++)
                    mma_bf16(acc[mt][nt], ah[mt], &bh[nt >> 1][(nt & 1) * 2]);

#pragma unroll
            for (int mt = 0; mt < 2; mt++) ldsm_x4(al[mt], sAl + aoff[mt]);
#pragma unroll
            for (int mt = 0; mt < 2; mt++)
#pragma unroll
                for (int nt = 0; nt < 8; nt++)
                    mma_bf16(acc[mt][nt], al[mt], &bh[nt >> 1][(nt & 1) * 2]);

#pragma unroll
            for (int ntp = 0; ntp < 4; ntp++) ldsm_x4(bl[ntp], sBl + boff[ntp]);
#pragma unroll
            for (int mt = 0; mt < 2; mt++)
#pragma unroll
                for (int nt = 0; nt < 8; nt++)
                    mma_bf16(acc[mt][nt], ah[mt], &bl[nt >> 1][(nt & 1) * 2]);
        }
        __syncthreads();
    }

    if (store_raw) {
        // partial pass: raw fp32 accum, no bias/relu
#pragma unroll
        for (int mt = 0; mt < 2; mt++) {
            int rbase = row0 + wm * 32 + mt * 16 + g;
#pragma unroll
            for (int nt = 0; nt < 8; nt++) {
                int col = n0 + wn * 64 + nt * 8 + th * 2;
                if (rbase < M)
                    *(float2*)(Cc + (size_t)rbase * 256 + col) =
                        make_float2(acc[mt][nt][0], acc[mt][nt][1]);
                if (rbase + 8 < M)
                    *(float2*)(Cc + (size_t)(rbase + 8) * 256 + col) =
                        make_float2(acc[mt][nt][2], acc[mt][nt][3]);
            }
        }
    } else if (!fuse_pool) {
#pragma unroll
        for (int mt = 0; mt < 2; mt++) {
            int rbase = row0 + wm * 32 + mt * 16 + g;
#pragma unroll
            for (int nt = 0; nt < 8; nt++) {
                int col = n0 + wn * 64 + nt * 8 + th * 2;
                float bx = bias[col], by = bias[col + 1];
                if (rbase < M) {
                    float2 p = Cacc ? *(const float2*)(Cacc + (size_t)rbase * 256 + col)
                                    : make_float2(0.f, 0.f);
                    float2 v0 = make_float2(fmaxf(acc[mt][nt][0] + bx + p.x, 0.f),
                                            fmaxf(acc[mt][nt][1] + by + p.y, 0.f));
                    *(float2*)(Cc + (size_t)rbase * 256 + col) = v0;
                    float hf0, hf1;
                    uint16_t h0 = bf_hi_bits(v0.x, hf0), h1 = bf_hi_bits(v0.y, hf1);
                    uint16_t l0 = bf_bits(v0.x - hf0),   l1 = bf_bits(v0.y - hf1);
                    size_t ob = (size_t)rbase * 512 + 256 + col;
                    *(uint32_t*)(oAh + ob) = (uint32_t)h0 | ((uint32_t)h1 << 16);
                    *(uint32_t*)(oAl + ob) = (uint32_t)l0 | ((uint32_t)l1 << 16);
                }
                if (rbase + 8 < M) {
                    float2 p = Cacc ? *(const float2*)(Cacc + (size_t)(rbase + 8) * 256 + col)
                                    : make_float2(0.f, 0.f);
                    float2 v1 = make_float2(fmaxf(acc[mt][nt][2] + bx + p.x, 0.f),
                                            fmaxf(acc[mt][nt][3] + by + p.y, 0.f));
                    *(float2*)(Cc + (size_t)(rbase + 8) * 256 + col) = v1;
                    float hf0, hf1;
                    uint16_t h0 = bf_hi_bits(v1.x, hf0), h1 = bf_hi_bits(v1.y, hf1);
                    uint16_t l0 = bf_bits(v1.x - hf0),   l1 = bf_bits(v1.y - hf1);
                    size_t ob = (size_t)(rbase + 8) * 512 + 256 + col;
                    *(uint32_t*)(oAh + ob) = (uint32_t)h0 | ((uint32_t)h1 << 16);
                    *(uint32_t*)(oAl + ob) = (uint32_t)l0 | ((uint32_t)l1 << 16);
                }
            }
        }
    } else {
        float* red = (float*)smraw;              // [128][66]
        int*   sbat = (int*)(smraw + 33792);     // [128]
#pragma unroll 1
        for (int h = 0; h < 2; h++) {
            __syncthreads();
            if (tid < 128) sbat[tid] = (row0 + tid < M) ? batchp[row0 + tid] : -1;
            if (wn == h) {
#pragma unroll
                for (int mt = 0; mt < 2; mt++) {
                    int rl = wm * 32 + mt * 16 + g;
#pragma unroll
                    for (int nt = 0; nt < 8; nt++) {
                        int cl = nt * 8 + th * 2;
                        int colg = n0 + h * 64 + cl;
                        float bx = bias[colg], by = bias[colg + 1];
                        float2 p0 = make_float2(0.f, 0.f), p1 = make_float2(0.f, 0.f);
                        if (Cacc) {
                            if (row0 + rl < M)
                                p0 = *(const float2*)(Cacc + (size_t)(row0 + rl) * 256 + colg);
                            if (row0 + rl + 8 < M)
                                p1 = *(const float2*)(Cacc + (size_t)(row0 + rl + 8) * 256 + colg);
                        }
                        red[rl * 66 + cl]       = fmaxf(acc[mt][nt][0] + bx + p0.x, 0.f);
                        red[rl * 66 + cl + 1]   = fmaxf(acc[mt][nt][1] + by + p0.y, 0.f);
                        red[(rl + 8) * 66 + cl]     = fmaxf(acc[mt][nt][2] + bx + p1.x, 0.f);
                        red[(rl + 8) * 66 + cl + 1] = fmaxf(acc[mt][nt][3] + by + p1.y, 0.f);
                    }
                }
            }
            __syncthreads();
            int cl = tid & 63, rh = tid >> 6;
            float run = 0.f; int cur = -1;
#pragma unroll 1
            for (int r = rh * 32; r < rh * 32 + 32; r++) {
                int gb = sbat[r];
                if (gb != cur) {
                    if (cur >= 0)
                        atomicAdd(&psum[(size_t)cur * 256 + n0 + h * 64 + cl], run);
                    run = 0.f; cur = gb;
                }
                if (gb >= 0) run += red[r * 66 + cl];
            }
            if (cur >= 0)
                atomicAdd(&psum[(size_t)cur * 256 + n0 + h * 64 + cl], run);
        }
    }
}

// ---------------- finalize pooled means ----------------
__global__ void finalize_kernel() {
    int i = blockIdx.x * blockDim.x + threadIdx.x;
    if (i >= N_GRAPHS * HID) return;
    float c = (float)g_gcnt[i >> 8];
    g_pool[i] = g_pool[i] / fmaxf(c, 1.f);
}

// ---------------- fp32 GEMM (head MLP only; small) ----------------
__global__ __launch_bounds__(256, 2) void gemm_bias_act(
    const float* __restrict__ A1, int K1, const float* __restrict__ B1,
    const float* __restrict__ bias, float* __restrict__ Cc,
    int M, int Nout, int do_relu)
{
    __shared__ float As[8][132];
    __shared__ float Bs[8][128];
    int tid = threadIdx.x;
    int tx = tid & 15, ty = tid >> 4;
    int row0 = blockIdx.x * 128;
    int col0 = blockIdx.y * 128;

    unsigned long long acc[8][4];
#pragma unroll
    for (int i = 0; i < 8; i++)
#pragma unroll
        for (int j = 0; j < 4; j++) acc[i][j] = 0ull;

    int lm = tid >> 1, lk = (tid & 1) * 4;
    int bk = tid >> 5, bn = (tid & 31) * 4;

#pragma unroll 1
    for (int k0 = 0; k0 < K1; k0 += 8) {
        float4 av = make_float4(0.f, 0.f, 0.f, 0.f);
        int r = row0 + lm;
        if (r < M) av = *(const float4*)(A1 + (size_t)r * K1 + k0 + lk);
        float4 bv = *(const float4*)(B1 + (size_t)(k0 + bk) * Nout + col0 + bn);
        __syncthreads();
        As[lk + 0][lm] = av.x; As[lk + 1][lm] = av.y;
        As[lk + 2][lm] = av.z; As[lk + 3][lm] = av.w;
        *(float4*)&Bs[bk][bn] = bv;
        __syncthreads();
#pragma unroll
        for (int k = 0; k < 8; k++) {
            float4 a0 = *(const float4*)&As[k][ty * 4];
            float4 a1 = *(const float4*)&As[k][64 + ty * 4];
            float4 b0 = *(const float4*)&Bs[k][tx * 4];
            float4 b1 = *(const float4*)&Bs[k][64 + tx * 4];
            unsigned long long bp[4];
            bp[0] = pk2(b0.x, b0.y); bp[1] = pk2(b0.z, b0.w);
            bp[2] = pk2(b1.x, b1.y); bp[3] = pk2(b1.z, b1.w);
            float a[8] = {a0.x, a0.y, a0.z, a0.w, a1.x, a1.y, a1.z, a1.w};
#pragma unroll
            for (int i = 0; i < 8; i++) {
                unsigned long long ai = dup2(a[i]);
                fma2(acc[i][0], ai, bp[0]);
                fma2(acc[i][1], ai, bp[1]);
                fma2(acc[i][2], ai, bp[2]);
                fma2(acc[i][3], ai, bp[3]);
            }
        }
    }
#pragma unroll
    for (int i = 0; i < 8; i++) {
        int r = row0 + ((i < 4) ? ty * 4 + i : 64 + ty * 4 + (i - 4));
        if (r >= M) continue;
#pragma unroll
        for (int j = 0; j < 4; j++) {
            int c = col0 + ((j < 2) ? tx * 4 + j * 2 : 64 + tx * 4 + (j - 2) * 2);
            float2 v = upk2(acc[i][j]);
            v.x += bias[c]; v.y += bias[c + 1];
            if (do_relu) { v.x = fmaxf(v.x, 0.f); v.y = fmaxf(v.y, 0.f); }
            *(float2*)(Cc + (size_t)r * Nout + c) = v;
        }
    }
}

// ---------------- launch ----------------
extern "C" void kernel_launch(void* const* d_in, const int* in_sizes, int n_in,
                              void* d_out, int out_size) {
    const float* x   = (const float*)d_in[0];
    const int*   ei  = (const int*)d_in[1];
    const int*   src = ei;
    const int*   dst = ei + N_EDGES;
    const int* batch = (const int*)d_in[2];
    const float* W1l = (const float*)d_in[3];
    const float* b1  = (const float*)d_in[4];
    const float* W1r = (const float*)d_in[5];
    const float* W2l = (const float*)d_in[6];
    const float* b2  = (const float*)d_in[7];
    const float* W2r = (const float*)d_in[8];
    const float* W3  = (const float*)d_in[9];
    const float* b3  = (const float*)d_in[10];
    const float* W4  = (const float*)d_in[11];
    const float* b4  = (const float*)d_in[12];
    float* out = (float*)d_out;

    void *p_h1, *p_p1, *p_pool, *p_hidden, *p_Ah, *p_Al, *p_B1h, *p_B1l, *p_B2h, *p_B2l;
    cudaGetSymbolAddress(&p_h1, g_h1);
    cudaGetSymbolAddress(&p_p1, g_part1);
    cudaGetSymbolAddress(&p_pool, g_pool);
    cudaGetSymbolAddress(&p_hidden, g_hidden);
    cudaGetSymbolAddress(&p_Ah, g_Ah);
    cudaGetSymbolAddress(&p_Al, g_Al);
    cudaGetSymbolAddress(&p_B1h, g_B1h);
    cudaGetSymbolAddress(&p_B1l, g_B1l);
    cudaGetSymbolAddress(&p_B2h, g_B2h);
    cudaGetSymbolAddress(&p_B2l, g_B2l);
    float* h1 = (float*)p_h1;
    float* part1 = (float*)p_p1;
    float* pooled = (float*)p_pool;
    float* hidden = (float*)p_hidden;
    uint16_t* Ah = (uint16_t*)p_Ah;
    uint16_t* Al = (uint16_t*)p_Al;
    uint16_t* B1h = (uint16_t*)p_B1h;
    uint16_t* B1l = (uint16_t*)p_B1l;
    uint16_t* B2h = (uint16_t*)p_B2h;
    uint16_t* B2l = (uint16_t*)p_B2l;

    static cudaStream_t s_aux = nullptr;
    static cudaEvent_t ev_fork = nullptr, ev_agg1 = nullptr, ev_g1b = nullptr,
                       ev_agg2 = nullptr, ev_g2b = nullptr;
    if (!s_aux) {
        cudaStreamCreateWithFlags(&s_aux, cudaStreamNonBlocking);
        cudaEventCreateWithFlags(&ev_fork, cudaEventDisableTiming);
        cudaEventCreateWithFlags(&ev_agg1, cudaEventDisableTiming);
        cudaEventCreateWithFlags(&ev_g1b, cudaEventDisableTiming);
        cudaEventCreateWithFlags(&ev_agg2, cudaEventDisableTiming);
        cudaEventCreateWithFlags(&ev_g2b, cudaEventDisableTiming);
    }

    const int TB = 256;
    const int NSCAN = (N_NODES + 1023) / 1024;
    const dim3 ggrid((N_NODES + 127) / 128, 2);

    // ---- fork: aux stream does splits + self-GEMM (gemm1a) ----
    cudaEventRecord(ev_fork, 0);
    cudaStreamWaitEvent(s_aux, ev_fork, 0);
    wsplit_kernel<<<(256 * 128 + TB - 1) / TB, TB, 0, s_aux>>>(W1r, 128, 128, B1h, B1l);
    xsplit_kernel<<<(N_NODES * 32 + TB - 1) / TB, TB, 0, s_aux>>>(x, Ah, Al);
    // gemm1a: part1 = x @ W1r   (raw partial) — overlaps CSR + agg1 on main
    hgemm_kernel<<<ggrid, 256, 0, s_aux>>>(Ah + 128, Al + 128, B1h + 128, B1l + 128, 128,
                                           nullptr, part1, nullptr, nullptr, nullptr,
                                           N_NODES, 1, nullptr, nullptr, 0);
    wsplit_kernel<<<(256 * 128 + TB - 1) / TB, TB, 0, s_aux>>>(W1l, 128, 0, B1h, B1l);
    wsplit_kernel<<<(256 * 256 + TB - 1) / TB, TB, 0, s_aux>>>(W2l, 256, 0, B2h, B2l);
    wsplit_kernel<<<(256 * 256 + TB - 1) / TB, TB, 0, s_aux>>>(W2r, 256, 256, B2h, B2l);

    // ---- main stream: CSR build + zero + agg1 ----
    zero_kernel<<<(N_GRAPHS * HID + TB - 1) / TB, TB>>>();
    hist_kernel<<<(N_EDGES + TB - 1) / TB, TB>>>(dst, batch);
    scan1_kernel<<<NSCAN, 1024>>>();
    scan2_kernel<<<1, 128>>>(NSCAN);
    scan3_kernel<<<NSCAN, 1024>>>();
    scatter_kernel<<<(N_EDGES + TB - 1) / TB, TB>>>(src, dst);
    agg_split_kernel<IN_CH><<<(N_NODES * 32 + TB - 1) / TB, TB>>>(x, Ah, Al);
    cudaEventRecord(ev_agg1, 0);

    // ---- gemm1b on aux: h1 = relu(agg @ W1l + b1 + part1), split h1 -> cols 256..511
    cudaStreamWaitEvent(s_aux, ev_agg1, 0);
    hgemm_kernel<<<ggrid, 256, 0, s_aux>>>(Ah, Al, B1h, B1l, 128, b1, h1, part1,
                                           Ah, Al, N_NODES, 0, nullptr, nullptr, 0);
    cudaEventRecord(ev_g1b, s_aux);

    // gemm2a on aux (right after gemm1b): part1 = h1 @ W2r — overlaps agg2 on main
    hgemm_kernel<<<ggrid, 256, 0, s_aux>>>(Ah + 256, Al + 256, B2h + 256, B2l + 256, 256,
                                           nullptr, part1, nullptr, nullptr, nullptr,
                                           N_NODES, 1, nullptr, nullptr, 0);

    // ---- main: agg2 (needs h1) ----
    cudaStreamWaitEvent(0, ev_g1b, 0);
    agg_split_kernel<HID><<<(N_NODES * 32 + TB - 1) / TB, TB>>>(h1, Ah, Al);
    cudaEventRecord(ev_agg2, 0);

    // ---- gemm2b on aux: pool += segsum(relu(agg @ W2l + b2 + part1)) ----
    cudaStreamWaitEvent(s_aux, ev_agg2, 0);
    hgemm_kernel<<<ggrid, 256, 0, s_aux>>>(Ah, Al, B2h, B2l, 256, b2, nullptr, part1,
                                           nullptr, nullptr, N_NODES, 0, batch, pooled, 1);
    cudaEventRecord(ev_g2b, s_aux);
    cudaStreamWaitEvent(0, ev_g2b, 0);

    // pooled means + MLP head (main stream)
    finalize_kernel<<<(N_GRAPHS * HID + TB - 1) / TB, TB>>>();
    {
        dim3 grid((N_GRAPHS + 127) / 128, HID / 128);
        gemm_bias_act<<<grid, 256>>>(pooled, HID, W3, b3, hidden, N_GRAPHS, HID, 1);
    }
    {
        dim3 grid((N_GRAPHS + 127) / 128, OUT_CH / 128);
        gemm_bias_act<<<grid, 256>>>(hidden, HID, W4, b4, out, N_GRAPHS, OUT_CH, 0);
    }
}

// round 11
// speedup vs baseline: 1.2036x; 1.2036x over previous
#include <cuda_runtime.h>
#include <cuda_bf16.h>
#include <cstdint>

#define N_NODES  100000
#define N_EDGES  1600000
#define IN_CH    128
#define HID      256
#define OUT_CH   128
#define N_GRAPHS 2048

// ---------------- scratch (device globals: no allocation allowed) ----------------
__device__ int   g_deg[N_NODES];
__device__ int   g_fill[N_NODES];
__device__ int   g_rowptr[N_NODES + 1];
__device__ int   g_col[N_EDGES];
__device__ int   g_part[128];
__device__ int   g_part2[128];
__device__ int   g_gcnt[N_GRAPHS];
__device__ uint16_t g_Ah[(size_t)N_NODES * 512];
__device__ uint16_t g_Al[(size_t)N_NODES * 512];
__device__ uint16_t g_B1h[256 * 512], g_B1l[256 * 512];
__device__ uint16_t g_B2h[256 * 512], g_B2l[256 * 512];
__device__ float g_pool  [N_GRAPHS * HID];
__device__ float g_hidden[N_GRAPHS * HID];

// ---------------- helpers ----------------
__device__ __forceinline__ uint16_t bf_hi_bits(float v, float& hf) {
    __nv_bfloat16 b = __float2bfloat16_rn(v);
    hf = __bfloat162float(b);
    return *(uint16_t*)&b;
}
__device__ __forceinline__ uint16_t bf_bits(float v) {
    __nv_bfloat16 b = __float2bfloat16_rn(v);
    return *(uint16_t*)&b;
}
__device__ __forceinline__ uint32_t smem_u32(const void* p) {
    uint32_t a;
    asm("{ .reg .u64 t; cvta.to.shared.u64 t, %1; cvt.u32.u64 %0, t; }" : "=r"(a) : "l"(p));
    return a;
}

// packed f32x2 helpers (head MLP GEMM)
__device__ __forceinline__ void fma2(unsigned long long& c, unsigned long long a, unsigned long long b) {
    asm("fma.rn.f32x2 %0, %1, %2, %3;" : "=l"(c) : "l"(a), "l"(b), "l"(c));
}
__device__ __forceinline__ unsigned long long pk2(float lo, float hi) {
    unsigned long long r; asm("mov.b64 %0, {%1, %2};" : "=l"(r) : "f"(lo), "f"(hi)); return r;
}
__device__ __forceinline__ unsigned long long dup2(float x) {
    unsigned long long r; asm("mov.b64 %0, {%1, %1};" : "=l"(r) : "f"(x)); return r;
}
__device__ __forceinline__ float2 upk2(unsigned long long v) {
    float2 r; asm("mov.b64 {%0, %1}, %2;" : "=f"(r.x), "=f"(r.y) : "l"(v)); return r;
}

// ---------------- CSR build + zero ----------------
__global__ void zero_kernel() {
    int i = blockIdx.x * blockDim.x + threadIdx.x;
    if (i < N_NODES) { g_deg[i] = 0; g_fill[i] = 0; }
    if (i < N_GRAPHS * HID) g_pool[i] = 0.f;
    if (i < N_GRAPHS) g_gcnt[i] = 0;
}
__global__ void hist_kernel(const int* __restrict__ dst, const int* __restrict__ batch) {
    int e = blockIdx.x * blockDim.x + threadIdx.x;
    if (e < N_EDGES) atomicAdd(&g_deg[dst[e]], 1);
    if (e < N_NODES) atomicAdd(&g_gcnt[batch[e]], 1);
}
__global__ void scan1_kernel() {
    __shared__ int sh[1024];
    int t = threadIdx.x;
    int i = blockIdx.x * 1024 + t;
    sh[t] = (i < N_NODES) ? g_deg[i] : 0;
    __syncthreads();
    for (int off = 512; off > 0; off >>= 1) {
        if (t < off) sh[t] += sh[t + off];
        __syncthreads();
    }
    if (t == 0) g_part[blockIdx.x] = sh[0];
}
__global__ void scan2_kernel(int nparts) {
    __shared__ int sh[128];
    int t = threadIdx.x;
    int v = (t < nparts) ? g_part[t] : 0;
    sh[t] = v;
    __syncthreads();
    for (int off = 1; off < 128; off <<= 1) {
        int nv = (t >= off) ? sh[t - off] : 0;
        __syncthreads();
        sh[t] += nv;
        __syncthreads();
    }
    if (t < nparts) g_part2[t] = sh[t] - v;
    if (t == 0) g_rowptr[N_NODES] = N_EDGES;
}
__global__ void scan3_kernel() {
    __shared__ int sh[1024];
    int t = threadIdx.x;
    int i = blockIdx.x * 1024 + t;
    int v = (i < N_NODES) ? g_deg[i] : 0;
    sh[t] = v;
    __syncthreads();
    for (int off = 1; off < 1024; off <<= 1) {
        int nv = (t >= off) ? sh[t - off] : 0;
        __syncthreads();
        sh[t] += nv;
        __syncthreads();
    }
    if (i < N_NODES) g_rowptr[i] = sh[t] - v + g_part2[blockIdx.x];
}
__global__ void scatter_kernel(const int* __restrict__ src, const int* __restrict__ dst) {
    int e = blockIdx.x * blockDim.x + threadIdx.x;
    if (e >= N_EDGES) return;
    int d = dst[e];
    int p = g_rowptr[d] + atomicAdd(&g_fill[d], 1);
    g_col[p] = src[e];
}

// ---------------- split writers ----------------
__device__ __forceinline__ void split_store4(uint16_t* Ah, uint16_t* Al, size_t base,
                                             float v0, float v1, float v2, float v3) {
    float hf0, hf1, hf2, hf3;
    uint16_t h0 = bf_hi_bits(v0, hf0), h1 = bf_hi_bits(v1, hf1);
    uint16_t h2 = bf_hi_bits(v2, hf2), h3 = bf_hi_bits(v3, hf3);
    uint16_t l0 = bf_bits(v0 - hf0), l1 = bf_bits(v1 - hf1);
    uint16_t l2 = bf_bits(v2 - hf2), l3 = bf_bits(v3 - hf3);
    *(uint2*)(Ah + base) = make_uint2((uint32_t)h0 | ((uint32_t)h1 << 16),
                                      (uint32_t)h2 | ((uint32_t)h3 << 16));
    *(uint2*)(Al + base) = make_uint2((uint32_t)l0 | ((uint32_t)l1 << 16),
                                      (uint32_t)l2 | ((uint32_t)l3 << 16));
}

// layer-1 mean aggregation (one warp per node, 2-way edge unroll) over fp32 x
__global__ void agg1_split_kernel(const float* __restrict__ feat,
                                  uint16_t* __restrict__ Ah, uint16_t* __restrict__ Al) {
    int w = (blockIdx.x * blockDim.x + threadIdx.x) >> 5;
    int lane = threadIdx.x & 31;
    if (w >= N_NODES) return;
    int beg = g_rowptr[w], end = g_rowptr[w + 1];
    float4 acc = make_float4(0.f, 0.f, 0.f, 0.f);
    int j = beg;
    for (; j + 1 < end; j += 2) {
        int s0 = g_col[j], s1 = g_col[j + 1];
        float4 t0 = ((const float4*)(feat + (size_t)s0 * 128))[lane];
        float4 t1 = ((const float4*)(feat + (size_t)s1 * 128))[lane];
        acc.x += t0.x + t1.x; acc.y += t0.y + t1.y;
        acc.z += t0.z + t1.z; acc.w += t0.w + t1.w;
    }
    if (j < end) {
        float4 t0 = ((const float4*)(feat + (size_t)g_col[j] * 128))[lane];
        acc.x += t0.x; acc.y += t0.y; acc.z += t0.z; acc.w += t0.w;
    }
    float inv = (end > beg) ? 1.f / (float)(end - beg) : 0.f;
    split_store4(Ah, Al, (size_t)w * 512 + (size_t)lane * 4,
                 acc.x * inv, acc.y * inv, acc.z * inv, acc.w * inv);
}

// layer-2 mean aggregation: gathers split h1 (panel cols 256..511) and reconstructs hi+lo
__device__ __forceinline__ void add8(float* acc, uint4 h, uint4 l) {
    const uint32_t* hp = (const uint32_t*)&h;
    const uint32_t* lp = (const uint32_t*)&l;
#pragma unroll
    for (int i = 0; i < 4; i++) {
        __nv_bfloat162 hb = *(__nv_bfloat162*)&hp[i];
        __nv_bfloat162 lb = *(__nv_bfloat162*)&lp[i];
        float2 hf = __bfloat1622float2(hb), lf = __bfloat1622float2(lb);
        acc[i * 2]     += hf.x + lf.x;
        acc[i * 2 + 1] += hf.y + lf.y;
    }
}

__global__ void agg2_split_kernel(const uint16_t* __restrict__ Ahp,
                                  const uint16_t* __restrict__ Alp,
                                  uint16_t* __restrict__ Ah, uint16_t* __restrict__ Al) {
    int w = (blockIdx.x * blockDim.x + threadIdx.x) >> 5;
    int lane = threadIdx.x & 31;
    if (w >= N_NODES) return;
    int beg = g_rowptr[w], end = g_rowptr[w + 1];
    float acc[8];
#pragma unroll
    for (int i = 0; i < 8; i++) acc[i] = 0.f;
    int j = beg;
    for (; j + 1 < end; j += 2) {
        int s0 = g_col[j], s1 = g_col[j + 1];
        size_t o0 = (size_t)s0 * 512 + 256 + lane * 8;
        size_t o1 = (size_t)s1 * 512 + 256 + lane * 8;
        uint4 h0 = *(const uint4*)(Ahp + o0);
        uint4 l0 = *(const uint4*)(Alp + o0);
        uint4 h1v = *(const uint4*)(Ahp + o1);
        uint4 l1v = *(const uint4*)(Alp + o1);
        add8(acc, h0, l0);
        add8(acc, h1v, l1v);
    }
    if (j < end) {
        size_t o0 = (size_t)g_col[j] * 512 + 256 + lane * 8;
        uint4 h0 = *(const uint4*)(Ahp + o0);
        uint4 l0 = *(const uint4*)(Alp + o0);
        add8(acc, h0, l0);
    }
    float inv = (end > beg) ? 1.f / (float)(end - beg) : 0.f;
    size_t base = (size_t)w * 512 + (size_t)lane * 8;
    split_store4(Ah, Al, base,     acc[0] * inv, acc[1] * inv, acc[2] * inv, acc[3] * inv);
    split_store4(Ah, Al, base + 4, acc[4] * inv, acc[5] * inv, acc[6] * inv, acc[7] * inv);
}

// split x (fp32 [N,128]) into A panel cols 128..255
__global__ void xsplit_kernel(const float* __restrict__ x,
                              uint16_t* __restrict__ Ah, uint16_t* __restrict__ Al) {
    int idx = blockIdx.x * blockDim.x + threadIdx.x;
    if (idx >= N_NODES * 32) return;
    int row = idx >> 5, q = idx & 31;
    float4 v = ((const float4*)x)[idx];
    split_store4(Ah, Al, (size_t)row * 512 + 128 + (size_t)q * 4, v.x, v.y, v.z, v.w);
}

// transpose + split weight W[Kw,256] into B panel
__global__ void wsplit_kernel(const float* __restrict__ W, int Kw, int cofs,
                              uint16_t* __restrict__ Bh, uint16_t* __restrict__ Bl) {
    int idx = blockIdx.x * blockDim.x + threadIdx.x;
    if (idx >= 256 * Kw) return;
    int n = idx / Kw, k = idx - n * Kw;
    float v = W[(size_t)k * 256 + n];
    float hf; uint16_t h = bf_hi_bits(v, hf);
    Bh[(size_t)n * 512 + cofs + k] = h;
    Bl[(size_t)n * 512 + cofs + k] = bf_bits(v - hf);
}

// ---------------- pre-split bf16 HMMA GEMM (register prefetch) ----------------
#define LDB_S 40

__device__ __forceinline__ void mma_bf16(float* c, const uint32_t* a, const uint32_t* b) {
    asm volatile(
        "mma.sync.aligned.m16n8k16.row.col.f32.bf16.bf16.f32 "
        "{%0,%1,%2,%3}, {%4,%5,%6,%7}, {%8,%9}, {%0,%1,%2,%3};"
        : "+f"(c[0]), "+f"(c[1]), "+f"(c[2]), "+f"(c[3])
        : "r"(a[0]), "r"(a[1]), "r"(a[2]), "r"(a[3]), "r"(b[0]), "r"(b[1]));
}
__device__ __forceinline__ void ldsm_x4(uint32_t* r, uint32_t addr) {
    asm volatile("ldmatrix.sync.aligned.m8n8.x4.shared.b16 {%0,%1,%2,%3}, [%4];"
                 : "=r"(r[0]), "=r"(r[1]), "=r"(r[2]), "=r"(r[3]) : "r"(addr));
}

__global__ __launch_bounds__(256, 1) void hgemm_kernel(
    const uint16_t* __restrict__ Ah, const uint16_t* __restrict__ Al,
    const uint16_t* __restrict__ Bh, const uint16_t* __restrict__ Bl,
    int K, const float* __restrict__ bias, float* __restrict__ Cc,
    uint16_t* __restrict__ oAh, uint16_t* __restrict__ oAl,
    int M, const int* __restrict__ batchp, float* __restrict__ psum, int fuse_pool)
{
    __shared__ __align__(16) uint8_t smraw[40960];
    uint16_t* As_h = (uint16_t*)(smraw);
    uint16_t* As_l = (uint16_t*)(smraw + 10240);
    uint16_t* Bs_h = (uint16_t*)(smraw + 20480);
    uint16_t* Bs_l = (uint16_t*)(smraw + 30720);

    const int tid = threadIdx.x;
    const int lane = tid & 31, wid = tid >> 5;
    const int wm = wid & 3, wn = wid >> 2;
    const int g = lane >> 2, th = lane & 3;
    const int row0 = blockIdx.x * 128;
    const int n0 = blockIdx.y * 128;

    const uint32_t sAh = smem_u32(smraw);
    const uint32_t sAl = sAh + 10240;
    const uint32_t sBh = sAh + 20480;
    const uint32_t sBl = sAh + 30720;

    const int nch = K >> 5;

    float acc[2][8][4];
#pragma unroll
    for (int mt = 0; mt < 2; mt++)
#pragma unroll
        for (int nt = 0; nt < 8; nt++)
#pragma unroll
            for (int r = 0; r < 4; r++) acc[mt][nt][r] = 0.f;

    const int lt = lane >> 3, lr = lane & 7;
    const int pr = tid >> 2, pq = tid & 3;

    uint4 ra_h[2], ra_l[2], rb_h[2], rb_l[2];

    {
#pragma unroll
        for (int i = 0; i < 2; i++) {
            int r = pr + i * 64;
            int ga = row0 + r;
            size_t ao = (size_t)ga * 512 + pq * 8;
            if (ga < M) { ra_h[i] = *(const uint4*)(Ah + ao); ra_l[i] = *(const uint4*)(Al + ao); }
            else        { ra_h[i] = make_uint4(0,0,0,0);      ra_l[i] = make_uint4(0,0,0,0); }
            size_t bo = (size_t)(n0 + r) * 512 + pq * 8;
            rb_h[i] = *(const uint4*)(Bh + bo);
            rb_l[i] = *(const uint4*)(Bl + bo);
        }
    }

#pragma unroll 1
    for (int c = 0; c < nch; c++) {
#pragma unroll
        for (int i = 0; i < 2; i++) {
            int r = pr + i * 64;
            int so = r * LDB_S + pq * 8;
            *(uint4*)&As_h[so] = ra_h[i];
            *(uint4*)&As_l[so] = ra_l[i];
            *(uint4*)&Bs_h[so] = rb_h[i];
            *(uint4*)&Bs_l[so] = rb_l[i];
        }
        __syncthreads();

        if (c + 1 < nch) {
            int kb = (c + 1) * 32;
#pragma unroll
            for (int i = 0; i < 2; i++) {
                int r = pr + i * 64;
                int ga = row0 + r;
                size_t ao = (size_t)ga * 512 + kb + pq * 8;
                if (ga < M) { ra_h[i] = *(const uint4*)(Ah + ao); ra_l[i] = *(const uint4*)(Al + ao); }
                else        { ra_h[i] = make_uint4(0,0,0,0);      ra_l[i] = make_uint4(0,0,0,0); }
                size_t bo = (size_t)(n0 + r) * 512 + kb + pq * 8;
                rb_h[i] = *(const uint4*)(Bh + bo);
                rb_l[i] = *(const uint4*)(Bl + bo);
            }
        }

#pragma unroll
        for (int step = 0; step < 2; step++) {
            const int k0 = step * 16;
            uint32_t aoff[2];
#pragma unroll
            for (int mt = 0; mt < 2; mt++) {
                int ar = wm * 32 + mt * 16 + (lt & 1) * 8 + lr;
                int ak = k0 + (lt >> 1) * 8;
                aoff[mt] = (uint32_t)(ar * LDB_S + ak) * 2;
            }
            uint32_t boff[4];
#pragma unroll
            for (int ntp = 0; ntp < 4; ntp++) {
                int nr = wn * 64 + ntp * 16 + (lt >> 1) * 8 + lr;
                int nk = k0 + (lt & 1) * 8;
                boff[ntp] = (uint32_t)(nr * LDB_S + nk) * 2;
            }

            uint32_t ah[2][4], al[2][4], bh[4][4], bl[4][4];
#pragma unroll
            for (int mt = 0; mt < 2; mt++) ldsm_x4(ah[mt], sAh + aoff[mt]);
#pragma unroll
            for (int ntp = 0; ntp < 4; ntp++) ldsm_x4(bh[ntp], sBh + boff[ntp]);
#pragma unroll
            for (int mt = 0; mt < 2; mt++)
#pragma unroll
                for (int nt = 0; nt < 8; nt++)
                    mma_bf16(acc[mt][nt], ah[mt], &bh[nt >> 1][(nt & 1) * 2]);

#pragma unroll
            for (int mt = 0; mt < 2; mt++) ldsm_x4(al[mt], sAl + aoff[mt]);
#pragma unroll
            for (int mt = 0; mt < 2; mt++)
#pragma unroll
                for (int nt = 0; nt < 8; nt++)
                    mma_bf16(acc[mt][nt], al[mt], &bh[nt >> 1][(nt & 1) * 2]);

#pragma unroll
            for (int ntp = 0; ntp < 4; ntp++) ldsm_x4(bl[ntp], sBl + boff[ntp]);
#pragma unroll
            for (int mt = 0; mt < 2; mt++)
#pragma unroll
                for (int nt = 0; nt < 8; nt++)
                    mma_bf16(acc[mt][nt], ah[mt], &bl[nt >> 1][(nt & 1) * 2]);
        }
        __syncthreads();
    }

    if (!fuse_pool) {
        // epilogue: bias + relu; optional fp32 store; split store to panel cols 256..511
#pragma unroll
        for (int mt = 0; mt < 2; mt++) {
            int rbase = row0 + wm * 32 + mt * 16 + g;
#pragma unroll
            for (int nt = 0; nt < 8; nt++) {
                int col = n0 + wn * 64 + nt * 8 + th * 2;
                float bx = bias[col], by = bias[col + 1];
                float2 v0 = make_float2(fmaxf(acc[mt][nt][0] + bx, 0.f),
                                        fmaxf(acc[mt][nt][1] + by, 0.f));
                float2 v1 = make_float2(fmaxf(acc[mt][nt][2] + bx, 0.f),
                                        fmaxf(acc[mt][nt][3] + by, 0.f));
                if (rbase < M) {
                    if (Cc) *(float2*)(Cc + (size_t)rbase * 256 + col) = v0;
                    float hf0, hf1;
                    uint16_t h0 = bf_hi_bits(v0.x, hf0), h1 = bf_hi_bits(v0.y, hf1);
                    uint16_t l0 = bf_bits(v0.x - hf0),   l1 = bf_bits(v0.y - hf1);
                    size_t ob = (size_t)rbase * 512 + 256 + col;
                    *(uint32_t*)(oAh + ob) = (uint32_t)h0 | ((uint32_t)h1 << 16);
                    *(uint32_t*)(oAl + ob) = (uint32_t)l0 | ((uint32_t)l1 << 16);
                }
                if (rbase + 8 < M) {
                    if (Cc) *(float2*)(Cc + (size_t)(rbase + 8) * 256 + col) = v1;
                    float hf0, hf1;
                    uint16_t h0 = bf_hi_bits(v1.x, hf0), h1 = bf_hi_bits(v1.y, hf1);
                    uint16_t l0 = bf_bits(v1.x - hf0),   l1 = bf_bits(v1.y - hf1);
                    size_t ob = (size_t)(rbase + 8) * 512 + 256 + col;
                    *(uint32_t*)(oAh + ob) = (uint32_t)h0 | ((uint32_t)h1 << 16);
                    *(uint32_t*)(oAl + ob) = (uint32_t)l0 | ((uint32_t)l1 << 16);
                }
            }
        }
    } else {
        float* red = (float*)smraw;              // [128][66]
        int*   sbat = (int*)(smraw + 33792);     // [128]
#pragma unroll 1
        for (int h = 0; h < 2; h++) {
            __syncthreads();
            if (tid < 128) sbat[tid] = (row0 + tid < M) ? batchp[row0 + tid] : -1;
            if (wn == h) {
#pragma unroll
                for (int mt = 0; mt < 2; mt++) {
                    int rl = wm * 32 + mt * 16 + g;
#pragma unroll
                    for (int nt = 0; nt < 8; nt++) {
                        int cl = nt * 8 + th * 2;
                        int colg = n0 + h * 64 + cl;
                        float bx = bias[colg], by = bias[colg + 1];
                        red[rl * 66 + cl]       = fmaxf(acc[mt][nt][0] + bx, 0.f);
                        red[rl * 66 + cl + 1]   = fmaxf(acc[mt][nt][1] + by, 0.f);
                        red[(rl + 8) * 66 + cl]     = fmaxf(acc[mt][nt][2] + bx, 0.f);
                        red[(rl + 8) * 66 + cl + 1] = fmaxf(acc[mt][nt][3] + by, 0.f);
                    }
                }
            }
            __syncthreads();
            int cl = tid & 63, rh = tid >> 6;
            float run = 0.f; int cur = -1;
#pragma unroll 1
            for (int r = rh * 32; r < rh * 32 + 32; r++) {
                int gb = sbat[r];
                if (gb != cur) {
                    if (cur >= 0)
                        atomicAdd(&psum[(size_t)cur * 256 + n0 + h * 64 + cl], run);
                    run = 0.f; cur = gb;
                }
                if (gb >= 0) run += red[r * 66 + cl];
            }
            if (cur >= 0)
                atomicAdd(&psum[(size_t)cur * 256 + n0 + h * 64 + cl], run);
        }
    }
}

// ---------------- finalize pooled means ----------------
__global__ void finalize_kernel() {
    int i = blockIdx.x * blockDim.x + threadIdx.x;
    if (i >= N_GRAPHS * HID) return;
    float c = (float)g_gcnt[i >> 8];
    g_pool[i] = g_pool[i] / fmaxf(c, 1.f);
}

// ---------------- fp32 GEMM (head MLP only; small) ----------------
__global__ __launch_bounds__(256, 2) void gemm_bias_act(
    const float* __restrict__ A1, int K1, const float* __restrict__ B1,
    const float* __restrict__ bias, float* __restrict__ Cc,
    int M, int Nout, int do_relu)
{
    __shared__ float As[8][132];
    __shared__ float Bs[8][128];
    int tid = threadIdx.x;
    int tx = tid & 15, ty = tid >> 4;
    int row0 = blockIdx.x * 128;
    int col0 = blockIdx.y * 128;

    unsigned long long acc[8][4];
#pragma unroll
    for (int i = 0; i < 8; i++)
#pragma unroll
        for (int j = 0; j < 4; j++) acc[i][j] = 0ull;

    int lm = tid >> 1, lk = (tid & 1) * 4;
    int bk = tid >> 5, bn = (tid & 31) * 4;

#pragma unroll 1
    for (int k0 = 0; k0 < K1; k0 += 8) {
        float4 av = make_float4(0.f, 0.f, 0.f, 0.f);
        int r = row0 + lm;
        if (r < M) av = *(const float4*)(A1 + (size_t)r * K1 + k0 + lk);
        float4 bv = *(const float4*)(B1 + (size_t)(k0 + bk) * Nout + col0 + bn);
        __syncthreads();
        As[lk + 0][lm] = av.x; As[lk + 1][lm] = av.y;
        As[lk + 2][lm] = av.z; As[lk + 3][lm] = av.w;
        *(float4*)&Bs[bk][bn] = bv;
        __syncthreads();
#pragma unroll
        for (int k = 0; k < 8; k++) {
            float4 a0 = *(const float4*)&As[k][ty * 4];
            float4 a1 = *(const float4*)&As[k][64 + ty * 4];
            float4 b0 = *(const float4*)&Bs[k][tx * 4];
            float4 b1 = *(const float4*)&Bs[k][64 + tx * 4];
            unsigned long long bp[4];
            bp[0] = pk2(b0.x, b0.y); bp[1] = pk2(b0.z, b0.w);
            bp[2] = pk2(b1.x, b1.y); bp[3] = pk2(b1.z, b1.w);
            float a[8] = {a0.x, a0.y, a0.z, a0.w, a1.x, a1.y, a1.z, a1.w};
#pragma unroll
            for (int i = 0; i < 8; i++) {
                unsigned long long ai = dup2(a[i]);
                fma2(acc[i][0], ai, bp[0]);
                fma2(acc[i][1], ai, bp[1]);
                fma2(acc[i][2], ai, bp[2]);
                fma2(acc[i][3], ai, bp[3]);
            }
        }
    }
#pragma unroll
    for (int i = 0; i < 8; i++) {
        int r = row0 + ((i < 4) ? ty * 4 + i : 64 + ty * 4 + (i - 4));
        if (r >= M) continue;
#pragma unroll
        for (int j = 0; j < 4; j++) {
            int c = col0 + ((j < 2) ? tx * 4 + j * 2 : 64 + tx * 4 + (j - 2) * 2);
            float2 v = upk2(acc[i][j]);
            v.x += bias[c]; v.y += bias[c + 1];
            if (do_relu) { v.x = fmaxf(v.x, 0.f); v.y = fmaxf(v.y, 0.f); }
            *(float2*)(Cc + (size_t)r * Nout + c) = v;
        }
    }
}

// ---------------- launch ----------------
extern "C" void kernel_launch(void* const* d_in, const int* in_sizes, int n_in,
                              void* d_out, int out_size) {
    const float* x   = (const float*)d_in[0];
    const int*   ei  = (const int*)d_in[1];
    const int*   src = ei;
    const int*   dst = ei + N_EDGES;
    const int* batch = (const int*)d_in[2];
    const float* W1l = (const float*)d_in[3];
    const float* b1  = (const float*)d_in[4];
    const float* W1r = (const float*)d_in[5];
    const float* W2l = (const float*)d_in[6];
    const float* b2  = (const float*)d_in[7];
    const float* W2r = (const float*)d_in[8];
    const float* W3  = (const float*)d_in[9];
    const float* b3  = (const float*)d_in[10];
    const float* W4  = (const float*)d_in[11];
    const float* b4  = (const float*)d_in[12];
    float* out = (float*)d_out;

    void *p_pool, *p_hidden, *p_Ah, *p_Al, *p_B1h, *p_B1l, *p_B2h, *p_B2l;
    cudaGetSymbolAddress(&p_pool, g_pool);
    cudaGetSymbolAddress(&p_hidden, g_hidden);
    cudaGetSymbolAddress(&p_Ah, g_Ah);
    cudaGetSymbolAddress(&p_Al, g_Al);
    cudaGetSymbolAddress(&p_B1h, g_B1h);
    cudaGetSymbolAddress(&p_B1l, g_B1l);
    cudaGetSymbolAddress(&p_B2h, g_B2h);
    cudaGetSymbolAddress(&p_B2l, g_B2l);
    float* pooled = (float*)p_pool;
    float* hidden = (float*)p_hidden;
    uint16_t* Ah = (uint16_t*)p_Ah;
    uint16_t* Al = (uint16_t*)p_Al;
    uint16_t* B1h = (uint16_t*)p_B1h;
    uint16_t* B1l = (uint16_t*)p_B1l;
    uint16_t* B2h = (uint16_t*)p_B2h;
    uint16_t* B2l = (uint16_t*)p_B2l;

    static cudaStream_t s_aux = nullptr;
    static cudaEvent_t ev_fork = nullptr, ev_join = nullptr;
    if (!s_aux) {
        cudaStreamCreateWithFlags(&s_aux, cudaStreamNonBlocking);
        cudaEventCreateWithFlags(&ev_fork, cudaEventDisableTiming);
        cudaEventCreateWithFlags(&ev_join, cudaEventDisableTiming);
    }

    const int TB = 256;
    const dim3 ggrid((N_NODES + 127) / 128, 2);
    const int NSCAN = (N_NODES + 1023) / 1024;

    // ---- fork: weight/x splits on aux stream ----
    cudaEventRecord(ev_fork, 0);
    cudaStreamWaitEvent(s_aux, ev_fork, 0);
    wsplit_kernel<<<(256 * 128 + TB - 1) / TB, TB, 0, s_aux>>>(W1l, 128, 0, B1h, B1l);
    wsplit_kernel<<<(256 * 128 + TB - 1) / TB, TB, 0, s_aux>>>(W1r, 128, 128, B1h, B1l);
    wsplit_kernel<<<(256 * 256 + TB - 1) / TB, TB, 0, s_aux>>>(W2l, 256, 0, B2h, B2l);
    wsplit_kernel<<<(256 * 256 + TB - 1) / TB, TB, 0, s_aux>>>(W2r, 256, 256, B2h, B2l);
    xsplit_kernel<<<(N_NODES * 32 + TB - 1) / TB, TB, 0, s_aux>>>(x, Ah, Al);
    cudaEventRecord(ev_join, s_aux);

    // ---- main stream: CSR build + zero pooled sums ----
    zero_kernel<<<(N_GRAPHS * HID + TB - 1) / TB, TB>>>();
    hist_kernel<<<(N_EDGES + TB - 1) / TB, TB>>>(dst, batch);
    scan1_kernel<<<NSCAN, 1024>>>();
    scan2_kernel<<<1, 128>>>(NSCAN);
    scan3_kernel<<<NSCAN, 1024>>>();
    scatter_kernel<<<(N_EDGES + TB - 1) / TB, TB>>>(src, dst);

    // Layer 1 aggregation (needs CSR + x only)
    agg1_split_kernel<<<(N_NODES * 32 + TB - 1) / TB, TB>>>(x, Ah, Al);

    // join before gemm1 (needs xsplit + weight splits)
    cudaStreamWaitEvent(0, ev_join, 0);
    // gemm1: split h1 -> panel cols 256..511 (no fp32 h1 buffer)
    hgemm_kernel<<<ggrid, 256>>>(Ah, Al, B1h, B1l, 256, b1, nullptr, Ah, Al, N_NODES,
                                 nullptr, nullptr, 0);

    // Layer 2: agg over split h1 panels, writes cols 0..255; then fused-pool GEMM K=512
    agg2_split_kernel<<<(N_NODES * 32 + TB - 1) / TB, TB>>>(Ah, Al, Ah, Al);
    hgemm_kernel<<<ggrid, 256>>>(Ah, Al, B2h, B2l, 512, b2, nullptr, nullptr, nullptr,
                                 N_NODES, batch, pooled, 1);

    // pooled means + MLP head
    finalize_kernel<<<(N_GRAPHS * HID + TB - 1) / TB, TB>>>();
    {
        dim3 grid((N_GRAPHS + 127) / 128, HID / 128);
        gemm_bias_act<<<grid, 256>>>(pooled, HID, W3, b3, hidden, N_GRAPHS, HID, 1);
    }
    {
        dim3 grid((N_GRAPHS + 127) / 128, OUT_CH / 128);
        gemm_bias_act<<<grid, 256>>>(hidden, HID, W4, b4, out, N_GRAPHS, OUT_CH, 0);
    }
}

// round 12
// speedup vs baseline: 1.3198x; 1.0965x over previous
#include <cuda_runtime.h>
#include <cuda_bf16.h>
#include <cstdint>

#define N_NODES  100000
#define N_EDGES  1600000
#define IN_CH    128
#define HID      256
#define OUT_CH   128
#define N_GRAPHS 2048

// ---------------- scratch (device globals: no allocation allowed) ----------------
__device__ int   g_deg[N_NODES];
__device__ int   g_fill[N_NODES];
__device__ int   g_rowptr[N_NODES + 1];
__device__ int   g_col[N_EDGES];
__device__ int   g_part[128];
__device__ int   g_part2[128];
__device__ int   g_gcnt[N_GRAPHS];
__device__ uint16_t g_Ah[(size_t)N_NODES * 512];
__device__ uint16_t g_Al[(size_t)N_NODES * 512];
__device__ uint16_t g_B1h[256 * 512], g_B1l[256 * 512];
__device__ uint16_t g_B2h[256 * 512], g_B2l[256 * 512];
__device__ float g_pool  [N_GRAPHS * HID];
__device__ float g_hidden[N_GRAPHS * HID];

// ---------------- helpers ----------------
__device__ __forceinline__ uint16_t bf_hi_bits(float v, float& hf) {
    __nv_bfloat16 b = __float2bfloat16_rn(v);
    hf = __bfloat162float(b);
    return *(uint16_t*)&b;
}
__device__ __forceinline__ uint16_t bf_bits(float v) {
    __nv_bfloat16 b = __float2bfloat16_rn(v);
    return *(uint16_t*)&b;
}
__device__ __forceinline__ uint32_t smem_u32(const void* p) {
    uint32_t a;
    asm("{ .reg .u64 t; cvta.to.shared.u64 t, %1; cvt.u32.u64 %0, t; }" : "=r"(a) : "l"(p));
    return a;
}

// packed f32x2 helpers (head MLP GEMM)
__device__ __forceinline__ void fma2(unsigned long long& c, unsigned long long a, unsigned long long b) {
    asm("fma.rn.f32x2 %0, %1, %2, %3;" : "=l"(c) : "l"(a), "l"(b), "l"(c));
}
__device__ __forceinline__ unsigned long long pk2(float lo, float hi) {
    unsigned long long r; asm("mov.b64 %0, {%1, %2};" : "=l"(r) : "f"(lo), "f"(hi)); return r;
}
__device__ __forceinline__ unsigned long long dup2(float x) {
    unsigned long long r; asm("mov.b64 %0, {%1, %1};" : "=l"(r) : "f"(x)); return r;
}
__device__ __forceinline__ float2 upk2(unsigned long long v) {
    float2 r; asm("mov.b64 {%0, %1}, %2;" : "=f"(r.x), "=f"(r.y) : "l"(v)); return r;
}

// ---------------- CSR build + zero ----------------
__global__ void zero_kernel() {
    int i = blockIdx.x * blockDim.x + threadIdx.x;
    if (i < N_NODES) { g_deg[i] = 0; g_fill[i] = 0; }
    if (i < N_GRAPHS * HID) g_pool[i] = 0.f;
    if (i < N_GRAPHS) g_gcnt[i] = 0;
}
__global__ void hist_kernel(const int* __restrict__ dst, const int* __restrict__ batch) {
    int e = blockIdx.x * blockDim.x + threadIdx.x;
    if (e < N_EDGES) atomicAdd(&g_deg[dst[e]], 1);
    if (e < N_NODES) atomicAdd(&g_gcnt[batch[e]], 1);
}
__global__ void scan1_kernel() {
    __shared__ int sh[1024];
    int t = threadIdx.x;
    int i = blockIdx.x * 1024 + t;
    sh[t] = (i < N_NODES) ? g_deg[i] : 0;
    __syncthreads();
    for (int off = 512; off > 0; off >>= 1) {
        if (t < off) sh[t] += sh[t + off];
        __syncthreads();
    }
    if (t == 0) g_part[blockIdx.x] = sh[0];
}
__global__ void scan2_kernel(int nparts) {
    __shared__ int sh[128];
    int t = threadIdx.x;
    int v = (t < nparts) ? g_part[t] : 0;
    sh[t] = v;
    __syncthreads();
    for (int off = 1; off < 128; off <<= 1) {
        int nv = (t >= off) ? sh[t - off] : 0;
        __syncthreads();
        sh[t] += nv;
        __syncthreads();
    }
    if (t < nparts) g_part2[t] = sh[t] - v;
    if (t == 0) g_rowptr[N_NODES] = N_EDGES;
}
__global__ void scan3_kernel() {
    __shared__ int sh[1024];
    int t = threadIdx.x;
    int i = blockIdx.x * 1024 + t;
    int v = (i < N_NODES) ? g_deg[i] : 0;
    sh[t] = v;
    __syncthreads();
    for (int off = 1; off < 1024; off <<= 1) {
        int nv = (t >= off) ? sh[t - off] : 0;
        __syncthreads();
        sh[t] += nv;
        __syncthreads();
    }
    if (i < N_NODES) g_rowptr[i] = sh[t] - v + g_part2[blockIdx.x];
}
__global__ void scatter_kernel(const int* __restrict__ src, const int* __restrict__ dst) {
    int e = blockIdx.x * blockDim.x + threadIdx.x;
    if (e >= N_EDGES) return;
    int d = dst[e];
    int p = g_rowptr[d] + atomicAdd(&g_fill[d], 1);
    g_col[p] = src[e];
}

// ---------------- split writers ----------------
__device__ __forceinline__ void split_store4(uint16_t* Ah, uint16_t* Al, size_t base,
                                             float v0, float v1, float v2, float v3) {
    float hf0, hf1, hf2, hf3;
    uint16_t h0 = bf_hi_bits(v0, hf0), h1 = bf_hi_bits(v1, hf1);
    uint16_t h2 = bf_hi_bits(v2, hf2), h3 = bf_hi_bits(v3, hf3);
    uint16_t l0 = bf_bits(v0 - hf0), l1 = bf_bits(v1 - hf1);
    uint16_t l2 = bf_bits(v2 - hf2), l3 = bf_bits(v3 - hf3);
    *(uint2*)(Ah + base) = make_uint2((uint32_t)h0 | ((uint32_t)h1 << 16),
                                      (uint32_t)h2 | ((uint32_t)h3 << 16));
    *(uint2*)(Al + base) = make_uint2((uint32_t)l0 | ((uint32_t)l1 << 16),
                                      (uint32_t)l2 | ((uint32_t)l3 << 16));
}

__device__ __forceinline__ void add4h(float* acc, uint2 h) {
    const uint32_t* hp = (const uint32_t*)&h;
#pragma unroll
    for (int i = 0; i < 2; i++) {
        __nv_bfloat162 hb = *(__nv_bfloat162*)&hp[i];
        float2 hf = __bfloat1622float2(hb);
        acc[i * 2]     += hf.x;
        acc[i * 2 + 1] += hf.y;
    }
}
__device__ __forceinline__ void add8h(float* acc, uint4 h) {
    const uint32_t* hp = (const uint32_t*)&h;
#pragma unroll
    for (int i = 0; i < 4; i++) {
        __nv_bfloat162 hb = *(__nv_bfloat162*)&hp[i];
        float2 hf = __bfloat1622float2(hb);
        acc[i * 2]     += hf.x;
        acc[i * 2 + 1] += hf.y;
    }
}

// layer-1 mean aggregation: gathers bf16-hi x (panel cols 128..255), writes cols 0..127
__global__ void agg1_split_kernel(const uint16_t* __restrict__ Ahp,
                                  uint16_t* __restrict__ Ah, uint16_t* __restrict__ Al) {
    int w = (blockIdx.x * blockDim.x + threadIdx.x) >> 5;
    int lane = threadIdx.x & 31;
    if (w >= N_NODES) return;
    int beg = g_rowptr[w], end = g_rowptr[w + 1];
    float acc[4];
#pragma unroll
    for (int i = 0; i < 4; i++) acc[i] = 0.f;
    int j = beg;
    for (; j + 1 < end; j += 2) {
        int s0 = g_col[j], s1 = g_col[j + 1];
        uint2 h0 = *(const uint2*)(Ahp + (size_t)s0 * 512 + 128 + lane * 4);
        uint2 h1 = *(const uint2*)(Ahp + (size_t)s1 * 512 + 128 + lane * 4);
        add4h(acc, h0);
        add4h(acc, h1);
    }
    if (j < end) {
        uint2 h0 = *(const uint2*)(Ahp + (size_t)g_col[j] * 512 + 128 + lane * 4);
        add4h(acc, h0);
    }
    float inv = (end > beg) ? 1.f / (float)(end - beg) : 0.f;
    split_store4(Ah, Al, (size_t)w * 512 + (size_t)lane * 4,
                 acc[0] * inv, acc[1] * inv, acc[2] * inv, acc[3] * inv);
}

// layer-2 mean aggregation: gathers bf16-hi h1 (panel cols 256..511), writes cols 0..255
__global__ void agg2_split_kernel(const uint16_t* __restrict__ Ahp,
                                  uint16_t* __restrict__ Ah, uint16_t* __restrict__ Al) {
    int w = (blockIdx.x * blockDim.x + threadIdx.x) >> 5;
    int lane = threadIdx.x & 31;
    if (w >= N_NODES) return;
    int beg = g_rowptr[w], end = g_rowptr[w + 1];
    float acc[8];
#pragma unroll
    for (int i = 0; i < 8; i++) acc[i] = 0.f;
    int j = beg;
    for (; j + 1 < end; j += 2) {
        int s0 = g_col[j], s1 = g_col[j + 1];
        uint4 h0 = *(const uint4*)(Ahp + (size_t)s0 * 512 + 256 + lane * 8);
        uint4 h1 = *(const uint4*)(Ahp + (size_t)s1 * 512 + 256 + lane * 8);
        add8h(acc, h0);
        add8h(acc, h1);
    }
    if (j < end) {
        uint4 h0 = *(const uint4*)(Ahp + (size_t)g_col[j] * 512 + 256 + lane * 8);
        add8h(acc, h0);
    }
    float inv = (end > beg) ? 1.f / (float)(end - beg) : 0.f;
    size_t base = (size_t)w * 512 + (size_t)lane * 8;
    split_store4(Ah, Al, base,     acc[0] * inv, acc[1] * inv, acc[2] * inv, acc[3] * inv);
    split_store4(Ah, Al, base + 4, acc[4] * inv, acc[5] * inv, acc[6] * inv, acc[7] * inv);
}

// split x (fp32 [N,128]) into A panel cols 128..255
__global__ void xsplit_kernel(const float* __restrict__ x,
                              uint16_t* __restrict__ Ah, uint16_t* __restrict__ Al) {
    int idx = blockIdx.x * blockDim.x + threadIdx.x;
    if (idx >= N_NODES * 32) return;
    int row = idx >> 5, q = idx & 31;
    float4 v = ((const float4*)x)[idx];
    split_store4(Ah, Al, (size_t)row * 512 + 128 + (size_t)q * 4, v.x, v.y, v.z, v.w);
}

// transpose + split weight W[Kw,256] into B panel
__global__ void wsplit_kernel(const float* __restrict__ W, int Kw, int cofs,
                              uint16_t* __restrict__ Bh, uint16_t* __restrict__ Bl) {
    int idx = blockIdx.x * blockDim.x + threadIdx.x;
    if (idx >= 256 * Kw) return;
    int n = idx / Kw, k = idx - n * Kw;
    float v = W[(size_t)k * 256 + n];
    float hf; uint16_t h = bf_hi_bits(v, hf);
    Bh[(size_t)n * 512 + cofs + k] = h;
    Bl[(size_t)n * 512 + cofs + k] = bf_bits(v - hf);
}

// ---------------- pre-split bf16 HMMA GEMM (register prefetch) ----------------
#define LDB_S 40

__device__ __forceinline__ void mma_bf16(float* c, const uint32_t* a, const uint32_t* b) {
    asm volatile(
        "mma.sync.aligned.m16n8k16.row.col.f32.bf16.bf16.f32 "
        "{%0,%1,%2,%3}, {%4,%5,%6,%7}, {%8,%9}, {%0,%1,%2,%3};"
        : "+f"(c[0]), "+f"(c[1]), "+f"(c[2]), "+f"(c[3])
        : "r"(a[0]), "r"(a[1]), "r"(a[2]), "r"(a[3]), "r"(b[0]), "r"(b[1]));
}
__device__ __forceinline__ void ldsm_x4(uint32_t* r, uint32_t addr) {
    asm volatile("ldmatrix.sync.aligned.m8n8.x4.shared.b16 {%0,%1,%2,%3}, [%4];"
                 : "=r"(r[0]), "=r"(r[1]), "=r"(r[2]), "=r"(r[3]) : "r"(addr));
}

__global__ __launch_bounds__(256, 1) void hgemm_kernel(
    const uint16_t* __restrict__ Ah, const uint16_t* __restrict__ Al,
    const uint16_t* __restrict__ Bh, const uint16_t* __restrict__ Bl,
    int K, const float* __restrict__ bias, float* __restrict__ Cc,
    uint16_t* __restrict__ oAh, uint16_t* __restrict__ oAl,
    int M, const int* __restrict__ batchp, float* __restrict__ psum, int fuse_pool)
{
    __shared__ __align__(16) uint8_t smraw[40960];
    uint16_t* As_h = (uint16_t*)(smraw);
    uint16_t* As_l = (uint16_t*)(smraw + 10240);
    uint16_t* Bs_h = (uint16_t*)(smraw + 20480);
    uint16_t* Bs_l = (uint16_t*)(smraw + 30720);

    const int tid = threadIdx.x;
    const int lane = tid & 31, wid = tid >> 5;
    const int wm = wid & 3, wn = wid >> 2;
    const int g = lane >> 2, th = lane & 3;
    const int row0 = blockIdx.x * 128;
    const int n0 = blockIdx.y * 128;

    const uint32_t sAh = smem_u32(smraw);
    const uint32_t sAl = sAh + 10240;
    const uint32_t sBh = sAh + 20480;
    const uint32_t sBl = sAh + 30720;

    const int nch = K >> 5;

    float acc[2][8][4];
#pragma unroll
    for (int mt = 0; mt < 2; mt++)
#pragma unroll
        for (int nt = 0; nt < 8; nt++)
#pragma unroll
            for (int r = 0; r < 4; r++) acc[mt][nt][r] = 0.f;

    const int lt = lane >> 3, lr = lane & 7;
    const int pr = tid >> 2, pq = tid & 3;

    uint4 ra_h[2], ra_l[2], rb_h[2], rb_l[2];

    {
#pragma unroll
        for (int i = 0; i < 2; i++) {
            int r = pr + i * 64;
            int ga = row0 + r;
            size_t ao = (size_t)ga * 512 + pq * 8;
            if (ga < M) { ra_h[i] = *(const uint4*)(Ah + ao); ra_l[i] = *(const uint4*)(Al + ao); }
            else        { ra_h[i] = make_uint4(0,0,0,0);      ra_l[i] = make_uint4(0,0,0,0); }
            size_t bo = (size_t)(n0 + r) * 512 + pq * 8;
            rb_h[i] = *(const uint4*)(Bh + bo);
            rb_l[i] = *(const uint4*)(Bl + bo);
        }
    }

#pragma unroll 1
    for (int c = 0; c < nch; c++) {
#pragma unroll
        for (int i = 0; i < 2; i++) {
            int r = pr + i * 64;
            int so = r * LDB_S + pq * 8;
            *(uint4*)&As_h[so] = ra_h[i];
            *(uint4*)&As_l[so] = ra_l[i];
            *(uint4*)&Bs_h[so] = rb_h[i];
            *(uint4*)&Bs_l[so] = rb_l[i];
        }
        __syncthreads();

        if (c + 1 < nch) {
            int kb = (c + 1) * 32;
#pragma unroll
            for (int i = 0; i < 2; i++) {
                int r = pr + i * 64;
                int ga = row0 + r;
                size_t ao = (size_t)ga * 512 + kb + pq * 8;
                if (ga < M) { ra_h[i] = *(const uint4*)(Ah + ao); ra_l[i] = *(const uint4*)(Al + ao); }
                else        { ra_h[i] = make_uint4(0,0,0,0);      ra_l[i] = make_uint4(0,0,0,0); }
                size_t bo = (size_t)(n0 + r) * 512 + kb + pq * 8;
                rb_h[i] = *(const uint4*)(Bh + bo);
                rb_l[i] = *(const uint4*)(Bl + bo);
            }
        }

#pragma unroll
        for (int step = 0; step < 2; step++) {
            const int k0 = step * 16;
            uint32_t aoff[2];
#pragma unroll
            for (int mt = 0; mt < 2; mt++) {
                int ar = wm * 32 + mt * 16 + (lt & 1) * 8 + lr;
                int ak = k0 + (lt >> 1) * 8;
                aoff[mt] = (uint32_t)(ar * LDB_S + ak) * 2;
            }
            uint32_t boff[4];
#pragma unroll
            for (int ntp = 0; ntp < 4; ntp++) {
                int nr = wn * 64 + ntp * 16 + (lt >> 1) * 8 + lr;
                int nk = k0 + (lt & 1) * 8;
                boff[ntp] = (uint32_t)(nr * LDB_S + nk) * 2;
            }

            uint32_t ah[2][4], al[2][4], bh[4][4], bl[4][4];
#pragma unroll
            for (int mt = 0; mt < 2; mt++) ldsm_x4(ah[mt], sAh + aoff[mt]);
#pragma unroll
            for (int ntp = 0; ntp < 4; ntp++) ldsm_x4(bh[ntp], sBh + boff[ntp]);
#pragma unroll
            for (int mt = 0; mt < 2; mt++)
#pragma unroll
                for (int nt = 0; nt < 8; nt++)
                    mma_bf16(acc[mt][nt], ah[mt], &bh[nt >> 1][(nt & 1) * 2]);

#pragma unroll
            for (int mt = 0; mt < 2; mt++) ldsm_x4(al[mt], sAl + aoff[mt]);
#pragma unroll
            for (int mt = 0; mt < 2; mt++)
#pragma unroll
                for (int nt = 0; nt < 8; nt++)
                    mma_bf16(acc[mt][nt], al[mt], &bh[nt >> 1][(nt & 1) * 2]);

#pragma unroll
            for (int ntp = 0; ntp < 4; ntp++) ldsm_x4(bl[ntp], sBl + boff[ntp]);
#pragma unroll
            for (int mt = 0; mt < 2; mt++)
#pragma unroll
                for (int nt = 0; nt < 8; nt++)
                    mma_bf16(acc[mt][nt], ah[mt], &bl[nt >> 1][(nt & 1) * 2]);
        }
        __syncthreads();
    }

    if (!fuse_pool) {
        // epilogue: bias + relu; split store to panel cols 256..511
#pragma unroll
        for (int mt = 0; mt < 2; mt++) {
            int rbase = row0 + wm * 32 + mt * 16 + g;
#pragma unroll
            for (int nt = 0; nt < 8; nt++) {
                int col = n0 + wn * 64 + nt * 8 + th * 2;
                float bx = bias[col], by = bias[col + 1];
                float2 v0 = make_float2(fmaxf(acc[mt][nt][0] + bx, 0.f),
                                        fmaxf(acc[mt][nt][1] + by, 0.f));
                float2 v1 = make_float2(fmaxf(acc[mt][nt][2] + bx, 0.f),
                                        fmaxf(acc[mt][nt][3] + by, 0.f));
                if (rbase < M) {
                    if (Cc) *(float2*)(Cc + (size_t)rbase * 256 + col) = v0;
                    float hf0, hf1;
                    uint16_t h0 = bf_hi_bits(v0.x, hf0), h1 = bf_hi_bits(v0.y, hf1);
                    uint16_t l0 = bf_bits(v0.x - hf0),   l1 = bf_bits(v0.y - hf1);
                    size_t ob = (size_t)rbase * 512 + 256 + col;
                    *(uint32_t*)(oAh + ob) = (uint32_t)h0 | ((uint32_t)h1 << 16);
                    *(uint32_t*)(oAl + ob) = (uint32_t)l0 | ((uint32_t)l1 << 16);
                }
                if (rbase + 8 < M) {
                    if (Cc) *(float2*)(Cc + (size_t)(rbase + 8) * 256 + col) = v1;
                    float hf0, hf1;
                    uint16_t h0 = bf_hi_bits(v1.x, hf0), h1 = bf_hi_bits(v1.y, hf1);
                    uint16_t l0 = bf_bits(v1.x - hf0),   l1 = bf_bits(v1.y - hf1);
                    size_t ob = (size_t)(rbase + 8) * 512 + 256 + col;
                    *(uint32_t*)(oAh + ob) = (uint32_t)h0 | ((uint32_t)h1 << 16);
                    *(uint32_t*)(oAl + ob) = (uint32_t)l0 | ((uint32_t)l1 << 16);
                }
            }
        }
    } else {
        float* red = (float*)smraw;              // [128][66]
        int*   sbat = (int*)(smraw + 33792);     // [128]
#pragma unroll 1
        for (int h = 0; h < 2; h++) {
            __syncthreads();
            if (tid < 128) sbat[tid] = (row0 + tid < M) ? batchp[row0 + tid] : -1;
            if (wn == h) {
#pragma unroll
                for (int mt = 0; mt < 2; mt++) {
                    int rl = wm * 32 + mt * 16 + g;
#pragma unroll
                    for (int nt = 0; nt < 8; nt++) {
                        int cl = nt * 8 + th * 2;
                        int colg = n0 + h * 64 + cl;
                        float bx = bias[colg], by = bias[colg + 1];
                        red[rl * 66 + cl]       = fmaxf(acc[mt][nt][0] + bx, 0.f);
                        red[rl * 66 + cl + 1]   = fmaxf(acc[mt][nt][1] + by, 0.f);
                        red[(rl + 8) * 66 + cl]     = fmaxf(acc[mt][nt][2] + bx, 0.f);
                        red[(rl + 8) * 66 + cl + 1] = fmaxf(acc[mt][nt][3] + by, 0.f);
                    }
                }
            }
            __syncthreads();
            int cl = tid & 63, rh = tid >> 6;
            float run = 0.f; int cur = -1;
#pragma unroll 1
            for (int r = rh * 32; r < rh * 32 + 32; r++) {
                int gb = sbat[r];
                if (gb != cur) {
                    if (cur >= 0)
                        atomicAdd(&psum[(size_t)cur * 256 + n0 + h * 64 + cl], run);
                    run = 0.f; cur = gb;
                }
                if (gb >= 0) run += red[r * 66 + cl];
            }
            if (cur >= 0)
                atomicAdd(&psum[(size_t)cur * 256 + n0 + h * 64 + cl], run);
        }
    }
}

// ---------------- finalize pooled means ----------------
__global__ void finalize_kernel() {
    int i = blockIdx.x * blockDim.x + threadIdx.x;
    if (i >= N_GRAPHS * HID) return;
    float c = (float)g_gcnt[i >> 8];
    g_pool[i] = g_pool[i] / fmaxf(c, 1.f);
}

// ---------------- fp32 GEMM (head MLP only; small) ----------------
__global__ __launch_bounds__(256, 2) void gemm_bias_act(
    const float* __restrict__ A1, int K1, const float* __restrict__ B1,
    const float* __restrict__ bias, float* __restrict__ Cc,
    int M, int Nout, int do_relu)
{
    __shared__ float As[8][132];
    __shared__ float Bs[8][128];
    int tid = threadIdx.x;
    int tx = tid & 15, ty = tid >> 4;
    int row0 = blockIdx.x * 128;
    int col0 = blockIdx.y * 128;

    unsigned long long acc[8][4];
#pragma unroll
    for (int i = 0; i < 8; i++)
#pragma unroll
        for (int j = 0; j < 4; j++) acc[i][j] = 0ull;

    int lm = tid >> 1, lk = (tid & 1) * 4;
    int bk = tid >> 5, bn = (tid & 31) * 4;

#pragma unroll 1
    for (int k0 = 0; k0 < K1; k0 += 8) {
        float4 av = make_float4(0.f, 0.f, 0.f, 0.f);
        int r = row0 + lm;
        if (r < M) av = *(const float4*)(A1 + (size_t)r * K1 + k0 + lk);
        float4 bv = *(const float4*)(B1 + (size_t)(k0 + bk) * Nout + col0 + bn);
        __syncthreads();
        As[lk + 0][lm] = av.x; As[lk + 1][lm] = av.y;
        As[lk + 2][lm] = av.z; As[lk + 3][lm] = av.w;
        *(float4*)&Bs[bk][bn] = bv;
        __syncthreads();
#pragma unroll
        for (int k = 0; k < 8; k++) {
            float4 a0 = *(const float4*)&As[k][ty * 4];
            float4 a1 = *(const float4*)&As[k][64 + ty * 4];
            float4 b0 = *(const float4*)&Bs[k][tx * 4];
            float4 b1 = *(const float4*)&Bs[k][64 + tx * 4];
            unsigned long long bp[4];
            bp[0] = pk2(b0.x, b0.y); bp[1] = pk2(b0.z, b0.w);
            bp[2] = pk2(b1.x, b1.y); bp[3] = pk2(b1.z, b1.w);
            float a[8] = {a0.x, a0.y, a0.z, a0.w, a1.x, a1.y, a1.z, a1.w};
#pragma unroll
            for (int i = 0; i < 8; i++) {
                unsigned long long ai = dup2(a[i]);
                fma2(acc[i][0], ai, bp[0]);
                fma2(acc[i][1], ai, bp[1]);
                fma2(acc[i][2], ai, bp[2]);
                fma2(acc[i][3], ai, bp[3]);
            }
        }
    }
#pragma unroll
    for (int i = 0; i < 8; i++) {
        int r = row0 + ((i < 4) ? ty * 4 + i : 64 + ty * 4 + (i - 4));
        if (r >= M) continue;
#pragma unroll
        for (int j = 0; j < 4; j++) {
            int c = col0 + ((j < 2) ? tx * 4 + j * 2 : 64 + tx * 4 + (j - 2) * 2);
            float2 v = upk2(acc[i][j]);
            v.x += bias[c]; v.y += bias[c + 1];
            if (do_relu) { v.x = fmaxf(v.x, 0.f); v.y = fmaxf(v.y, 0.f); }
            *(float2*)(Cc + (size_t)r * Nout + c) = v;
        }
    }
}

// ---------------- launch ----------------
extern "C" void kernel_launch(void* const* d_in, const int* in_sizes, int n_in,
                              void* d_out, int out_size) {
    const float* x   = (const float*)d_in[0];
    const int*   ei  = (const int*)d_in[1];
    const int*   src = ei;
    const int*   dst = ei + N_EDGES;
    const int* batch = (const int*)d_in[2];
    const float* W1l = (const float*)d_in[3];
    const float* b1  = (const float*)d_in[4];
    const float* W1r = (const float*)d_in[5];
    const float* W2l = (const float*)d_in[6];
    const float* b2  = (const float*)d_in[7];
    const float* W2r = (const float*)d_in[8];
    const float* W3  = (const float*)d_in[9];
    const float* b3  = (const float*)d_in[10];
    const float* W4  = (const float*)d_in[11];
    const float* b4  = (const float*)d_in[12];
    float* out = (float*)d_out;

    void *p_pool, *p_hidden, *p_Ah, *p_Al, *p_B1h, *p_B1l, *p_B2h, *p_B2l;
    cudaGetSymbolAddress(&p_pool, g_pool);
    cudaGetSymbolAddress(&p_hidden, g_hidden);
    cudaGetSymbolAddress(&p_Ah, g_Ah);
    cudaGetSymbolAddress(&p_Al, g_Al);
    cudaGetSymbolAddress(&p_B1h, g_B1h);
    cudaGetSymbolAddress(&p_B1l, g_B1l);
    cudaGetSymbolAddress(&p_B2h, g_B2h);
    cudaGetSymbolAddress(&p_B2l, g_B2l);
    float* pooled = (float*)p_pool;
    float* hidden = (float*)p_hidden;
    uint16_t* Ah = (uint16_t*)p_Ah;
    uint16_t* Al = (uint16_t*)p_Al;
    uint16_t* B1h = (uint16_t*)p_B1h;
    uint16_t* B1l = (uint16_t*)p_B1l;
    uint16_t* B2h = (uint16_t*)p_B2h;
    uint16_t* B2l = (uint16_t*)p_B2l;

    static cudaStream_t s_aux = nullptr;
    static cudaEvent_t ev_fork = nullptr, ev_join = nullptr;
    if (!s_aux) {
        cudaStreamCreateWithFlags(&s_aux, cudaStreamNonBlocking);
        cudaEventCreateWithFlags(&ev_fork, cudaEventDisableTiming);
        cudaEventCreateWithFlags(&ev_join, cudaEventDisableTiming);
    }

    const int TB = 256;
    const dim3 ggrid((N_NODES + 127) / 128, 2);
    const int NSCAN = (N_NODES + 1023) / 1024;

    // ---- fork: weight/x splits on aux stream ----
    cudaEventRecord(ev_fork, 0);
    cudaStreamWaitEvent(s_aux, ev_fork, 0);
    xsplit_kernel<<<(N_NODES * 32 + TB - 1) / TB, TB, 0, s_aux>>>(x, Ah, Al);
    wsplit_kernel<<<(256 * 128 + TB - 1) / TB, TB, 0, s_aux>>>(W1l, 128, 0, B1h, B1l);
    wsplit_kernel<<<(256 * 128 + TB - 1) / TB, TB, 0, s_aux>>>(W1r, 128, 128, B1h, B1l);
    wsplit_kernel<<<(256 * 256 + TB - 1) / TB, TB, 0, s_aux>>>(W2l, 256, 0, B2h, B2l);
    wsplit_kernel<<<(256 * 256 + TB - 1) / TB, TB, 0, s_aux>>>(W2r, 256, 256, B2h, B2l);
    cudaEventRecord(ev_join, s_aux);

    // ---- main stream: CSR build + zero pooled sums ----
    zero_kernel<<<(N_GRAPHS * HID + TB - 1) / TB, TB>>>();
    hist_kernel<<<(N_EDGES + TB - 1) / TB, TB>>>(dst, batch);
    scan1_kernel<<<NSCAN, 1024>>>();
    scan2_kernel<<<1, 128>>>(NSCAN);
    scan3_kernel<<<NSCAN, 1024>>>();
    scatter_kernel<<<(N_EDGES + TB - 1) / TB, TB>>>(src, dst);

    // join before agg1 (needs xsplit hi panel); splits finish well before CSR chain
    cudaStreamWaitEvent(0, ev_join, 0);

    // Layer 1: agg over hi-x panel (cols 128..255) -> cols 0..127; gemm1 K=256
    agg1_split_kernel<<<(N_NODES * 32 + TB - 1) / TB, TB>>>(Ah, Ah, Al);
    hgemm_kernel<<<ggrid, 256>>>(Ah, Al, B1h, B1l, 256, b1, nullptr, Ah, Al, N_NODES,
                                 nullptr, nullptr, 0);

    // Layer 2: agg over hi-h1 panel (cols 256..511) -> cols 0..255; fused-pool GEMM K=512
    agg2_split_kernel<<<(N_NODES * 32 + TB - 1) / TB, TB>>>(Ah, Ah, Al);
    hgemm_kernel<<<ggrid, 256>>>(Ah, Al, B2h, B2l, 512, b2, nullptr, nullptr, nullptr,
                                 N_NODES, batch, pooled, 1);

    // pooled means + MLP head
    finalize_kernel<<<(N_GRAPHS * HID + TB - 1) / TB, TB>>>();
    {
        dim3 grid((N_GRAPHS + 127) / 128, HID / 128);
        gemm_bias_act<<<grid, 256>>>(pooled, HID, W3, b3, hidden, N_GRAPHS, HID, 1);
    }
    {
        dim3 grid((N_GRAPHS + 127) / 128, OUT_CH / 128);
        gemm_bias_act<<<grid, 256>>>(hidden, HID, W4, b4, out, N_GRAPHS, OUT_CH, 0);
    }
}

// round 13
// speedup vs baseline: 1.6000x; 1.2123x over previous
#include <cuda_runtime.h>
#include <cuda_bf16.h>
#include <cstdint>

#define N_NODES  100000
#define N_EDGES  1600000
#define IN_CH    128
#define HID      256
#define OUT_CH   128
#define N_GRAPHS 2048

// ---------------- scratch (device globals: no allocation allowed) ----------------
__device__ int   g_deg[N_NODES];
__device__ int   g_fill[N_NODES];
__device__ int   g_rowptr[N_NODES + 1];
__device__ int   g_col[N_EDGES];
__device__ int   g_part[128];
__device__ int   g_part2[128];
__device__ int   g_gcnt[N_GRAPHS];
__device__ uint16_t g_Ah[(size_t)N_NODES * 512];     // bf16-hi A panel (stride 512)
__device__ uint16_t g_B1h[256 * 512], g_B1l[256 * 512];
__device__ uint16_t g_B2h[256 * 512], g_B2l[256 * 512];
__device__ float g_pool  [N_GRAPHS * HID];
__device__ float g_hidden[N_GRAPHS * HID];

// ---------------- helpers ----------------
__device__ __forceinline__ uint16_t bf_hi_bits(float v, float& hf) {
    __nv_bfloat16 b = __float2bfloat16_rn(v);
    hf = __bfloat162float(b);
    return *(uint16_t*)&b;
}
__device__ __forceinline__ uint16_t bf_bits(float v) {
    __nv_bfloat16 b = __float2bfloat16_rn(v);
    return *(uint16_t*)&b;
}
__device__ __forceinline__ uint32_t smem_u32(const void* p) {
    uint32_t a;
    asm("{ .reg .u64 t; cvta.to.shared.u64 t, %1; cvt.u32.u64 %0, t; }" : "=r"(a) : "l"(p));
    return a;
}

// packed f32x2 helpers (head MLP GEMM)
__device__ __forceinline__ void fma2(unsigned long long& c, unsigned long long a, unsigned long long b) {
    asm("fma.rn.f32x2 %0, %1, %2, %3;" : "=l"(c) : "l"(a), "l"(b), "l"(c));
}
__device__ __forceinline__ unsigned long long pk2(float lo, float hi) {
    unsigned long long r; asm("mov.b64 %0, {%1, %2};" : "=l"(r) : "f"(lo), "f"(hi)); return r;
}
__device__ __forceinline__ unsigned long long dup2(float x) {
    unsigned long long r; asm("mov.b64 %0, {%1, %1};" : "=l"(r) : "f"(x)); return r;
}
__device__ __forceinline__ float2 upk2(unsigned long long v) {
    float2 r; asm("mov.b64 {%0, %1}, %2;" : "=f"(r.x), "=f"(r.y) : "l"(v)); return r;
}

// ---------------- CSR build + zero ----------------
__global__ void zero_kernel() {
    int i = blockIdx.x * blockDim.x + threadIdx.x;
    if (i < N_NODES) { g_deg[i] = 0; g_fill[i] = 0; }
    if (i < N_GRAPHS * HID) g_pool[i] = 0.f;
    if (i < N_GRAPHS) g_gcnt[i] = 0;
}
__global__ void hist_kernel(const int* __restrict__ dst, const int* __restrict__ batch) {
    int e = blockIdx.x * blockDim.x + threadIdx.x;
    if (e < N_EDGES) atomicAdd(&g_deg[dst[e]], 1);
    if (e < N_NODES) atomicAdd(&g_gcnt[batch[e]], 1);
}
__global__ void scan1_kernel() {
    __shared__ int sh[1024];
    int t = threadIdx.x;
    int i = blockIdx.x * 1024 + t;
    sh[t] = (i < N_NODES) ? g_deg[i] : 0;
    __syncthreads();
    for (int off = 512; off > 0; off >>= 1) {
        if (t < off) sh[t] += sh[t + off];
        __syncthreads();
    }
    if (t == 0) g_part[blockIdx.x] = sh[0];
}
__global__ void scan2_kernel(int nparts) {
    __shared__ int sh[128];
    int t = threadIdx.x;
    int v = (t < nparts) ? g_part[t] : 0;
    sh[t] = v;
    __syncthreads();
    for (int off = 1; off < 128; off <<= 1) {
        int nv = (t >= off) ? sh[t - off] : 0;
        __syncthreads();
        sh[t] += nv;
        __syncthreads();
    }
    if (t < nparts) g_part2[t] = sh[t] - v;
    if (t == 0) g_rowptr[N_NODES] = N_EDGES;
}
__global__ void scan3_kernel() {
    __shared__ int sh[1024];
    int t = threadIdx.x;
    int i = blockIdx.x * 1024 + t;
    int v = (i < N_NODES) ? g_deg[i] : 0;
    sh[t] = v;
    __syncthreads();
    for (int off = 1; off < 1024; off <<= 1) {
        int nv = (t >= off) ? sh[t - off] : 0;
        __syncthreads();
        sh[t] += nv;
        __syncthreads();
    }
    if (i < N_NODES) g_rowptr[i] = sh[t] - v + g_part2[blockIdx.x];
}
__global__ void scatter_kernel(const int* __restrict__ src, const int* __restrict__ dst) {
    int e = blockIdx.x * blockDim.x + threadIdx.x;
    if (e >= N_EDGES) return;
    int d = dst[e];
    int p = g_rowptr[d] + atomicAdd(&g_fill[d], 1);
    g_col[p] = src[e];
}

// ---------------- hi-only writers ----------------
__device__ __forceinline__ void hi_store4(uint16_t* Ah, size_t base,
                                          float v0, float v1, float v2, float v3) {
    uint16_t h0 = bf_bits(v0), h1 = bf_bits(v1), h2 = bf_bits(v2), h3 = bf_bits(v3);
    *(uint2*)(Ah + base) = make_uint2((uint32_t)h0 | ((uint32_t)h1 << 16),
                                      (uint32_t)h2 | ((uint32_t)h3 << 16));
}

__device__ __forceinline__ void add4h(float* acc, uint2 h) {
    const uint32_t* hp = (const uint32_t*)&h;
#pragma unroll
    for (int i = 0; i < 2; i++) {
        __nv_bfloat162 hb = *(__nv_bfloat162*)&hp[i];
        float2 hf = __bfloat1622float2(hb);
        acc[i * 2]     += hf.x;
        acc[i * 2 + 1] += hf.y;
    }
}
__device__ __forceinline__ void add8h(float* acc, uint4 h) {
    const uint32_t* hp = (const uint32_t*)&h;
#pragma unroll
    for (int i = 0; i < 4; i++) {
        __nv_bfloat162 hb = *(__nv_bfloat162*)&hp[i];
        float2 hf = __bfloat1622float2(hb);
        acc[i * 2]     += hf.x;
        acc[i * 2 + 1] += hf.y;
    }
}

// layer-1 mean aggregation: gathers bf16-hi x (panel cols 128..255), writes cols 0..127
__global__ void agg1_split_kernel(const uint16_t* __restrict__ Ahp,
                                  uint16_t* __restrict__ Ah) {
    int w = (blockIdx.x * blockDim.x + threadIdx.x) >> 5;
    int lane = threadIdx.x & 31;
    if (w >= N_NODES) return;
    int beg = g_rowptr[w], end = g_rowptr[w + 1];
    float acc[4];
#pragma unroll
    for (int i = 0; i < 4; i++) acc[i] = 0.f;
    int j = beg;
    for (; j + 1 < end; j += 2) {
        int s0 = g_col[j], s1 = g_col[j + 1];
        uint2 h0 = *(const uint2*)(Ahp + (size_t)s0 * 512 + 128 + lane * 4);
        uint2 h1 = *(const uint2*)(Ahp + (size_t)s1 * 512 + 128 + lane * 4);
        add4h(acc, h0);
        add4h(acc, h1);
    }
    if (j < end) {
        uint2 h0 = *(const uint2*)(Ahp + (size_t)g_col[j] * 512 + 128 + lane * 4);
        add4h(acc, h0);
    }
    float inv = (end > beg) ? 1.f / (float)(end - beg) : 0.f;
    hi_store4(Ah, (size_t)w * 512 + (size_t)lane * 4,
              acc[0] * inv, acc[1] * inv, acc[2] * inv, acc[3] * inv);
}

// layer-2 mean aggregation: gathers bf16-hi h1 (panel cols 256..511), writes cols 0..255
__global__ void agg2_split_kernel(const uint16_t* __restrict__ Ahp,
                                  uint16_t* __restrict__ Ah) {
    int w = (blockIdx.x * blockDim.x + threadIdx.x) >> 5;
    int lane = threadIdx.x & 31;
    if (w >= N_NODES) return;
    int beg = g_rowptr[w], end = g_rowptr[w + 1];
    float acc[8];
#pragma unroll
    for (int i = 0; i < 8; i++) acc[i] = 0.f;
    int j = beg;
    for (; j + 1 < end; j += 2) {
        int s0 = g_col[j], s1 = g_col[j + 1];
        uint4 h0 = *(const uint4*)(Ahp + (size_t)s0 * 512 + 256 + lane * 8);
        uint4 h1 = *(const uint4*)(Ahp + (size_t)s1 * 512 + 256 + lane * 8);
        add8h(acc, h0);
        add8h(acc, h1);
    }
    if (j < end) {
        uint4 h0 = *(const uint4*)(Ahp + (size_t)g_col[j] * 512 + 256 + lane * 8);
        add8h(acc, h0);
    }
    float inv = (end > beg) ? 1.f / (float)(end - beg) : 0.f;
    size_t base = (size_t)w * 512 + (size_t)lane * 8;
    hi_store4(Ah, base,     acc[0] * inv, acc[1] * inv, acc[2] * inv, acc[3] * inv);
    hi_store4(Ah, base + 4, acc[4] * inv, acc[5] * inv, acc[6] * inv, acc[7] * inv);
}

// convert x (fp32 [N,128]) into A panel cols 128..255 (hi only)
__global__ void xsplit_kernel(const float* __restrict__ x, uint16_t* __restrict__ Ah) {
    int idx = blockIdx.x * blockDim.x + threadIdx.x;
    if (idx >= N_NODES * 32) return;
    int row = idx >> 5, q = idx & 31;
    float4 v = ((const float4*)x)[idx];
    hi_store4(Ah, (size_t)row * 512 + 128 + (size_t)q * 4, v.x, v.y, v.z, v.w);
}

// transpose + split weight W[Kw,256] into B panel (hi + lo kept: weight error is systematic)
__global__ void wsplit_kernel(const float* __restrict__ W, int Kw, int cofs,
                              uint16_t* __restrict__ Bh, uint16_t* __restrict__ Bl) {
    int idx = blockIdx.x * blockDim.x + threadIdx.x;
    if (idx >= 256 * Kw) return;
    int n = idx / Kw, k = idx - n * Kw;
    float v = W[(size_t)k * 256 + n];
    float hf; uint16_t h = bf_hi_bits(v, hf);
    Bh[(size_t)n * 512 + cofs + k] = h;
    Bl[(size_t)n * 512 + cofs + k] = bf_bits(v - hf);
}

// ---------------- 2-pass bf16 HMMA GEMM: D = Ah*Bh + Ah*Bl ----------------
#define LDB_S 40

__device__ __forceinline__ void mma_bf16(float* c, const uint32_t* a, const uint32_t* b) {
    asm volatile(
        "mma.sync.aligned.m16n8k16.row.col.f32.bf16.bf16.f32 "
        "{%0,%1,%2,%3}, {%4,%5,%6,%7}, {%8,%9}, {%0,%1,%2,%3};"
        : "+f"(c[0]), "+f"(c[1]), "+f"(c[2]), "+f"(c[3])
        : "r"(a[0]), "r"(a[1]), "r"(a[2]), "r"(a[3]), "r"(b[0]), "r"(b[1]));
}
__device__ __forceinline__ void ldsm_x4(uint32_t* r, uint32_t addr) {
    asm volatile("ldmatrix.sync.aligned.m8n8.x4.shared.b16 {%0,%1,%2,%3}, [%4];"
                 : "=r"(r[0]), "=r"(r[1]), "=r"(r[2]), "=r"(r[3]) : "r"(addr));
}

__global__ __launch_bounds__(256, 1) void hgemm_kernel(
    const uint16_t* __restrict__ Ah,
    const uint16_t* __restrict__ Bh, const uint16_t* __restrict__ Bl,
    int K, const float* __restrict__ bias,
    uint16_t* __restrict__ oAh,
    int M, const int* __restrict__ batchp, float* __restrict__ psum, int fuse_pool)
{
    __shared__ __align__(16) uint8_t smraw[33792];   // Ah 10240 + Bh 10240 + Bl 10240 (+pool scratch reuse)
    uint16_t* As_h = (uint16_t*)(smraw);
    uint16_t* Bs_h = (uint16_t*)(smraw + 10240);
    uint16_t* Bs_l = (uint16_t*)(smraw + 20480);

    const int tid = threadIdx.x;
    const int lane = tid & 31, wid = tid >> 5;
    const int wm = wid & 3, wn = wid >> 2;
    const int g = lane >> 2, th = lane & 3;
    const int row0 = blockIdx.x * 128;
    const int n0 = blockIdx.y * 128;

    const uint32_t sAh = smem_u32(smraw);
    const uint32_t sBh = sAh + 10240;
    const uint32_t sBl = sAh + 20480;

    const int nch = K >> 5;

    float acc[2][8][4];
#pragma unroll
    for (int mt = 0; mt < 2; mt++)
#pragma unroll
        for (int nt = 0; nt < 8; nt++)
#pragma unroll
            for (int r = 0; r < 4; r++) acc[mt][nt][r] = 0.f;

    const int lt = lane >> 3, lr = lane & 7;
    const int pr = tid >> 2, pq = tid & 3;

    uint4 ra_h[2], rb_h[2], rb_l[2];

    {
#pragma unroll
        for (int i = 0; i < 2; i++) {
            int r = pr + i * 64;
            int ga = row0 + r;
            size_t ao = (size_t)ga * 512 + pq * 8;
            ra_h[i] = (ga < M) ? *(const uint4*)(Ah + ao) : make_uint4(0, 0, 0, 0);
            size_t bo = (size_t)(n0 + r) * 512 + pq * 8;
            rb_h[i] = *(const uint4*)(Bh + bo);
            rb_l[i] = *(const uint4*)(Bl + bo);
        }
    }

#pragma unroll 1
    for (int c = 0; c < nch; c++) {
#pragma unroll
        for (int i = 0; i < 2; i++) {
            int r = pr + i * 64;
            int so = r * LDB_S + pq * 8;
            *(uint4*)&As_h[so] = ra_h[i];
            *(uint4*)&Bs_h[so] = rb_h[i];
            *(uint4*)&Bs_l[so] = rb_l[i];
        }
        __syncthreads();

        if (c + 1 < nch) {
            int kb = (c + 1) * 32;
#pragma unroll
            for (int i = 0; i < 2; i++) {
                int r = pr + i * 64;
                int ga = row0 + r;
                size_t ao = (size_t)ga * 512 + kb + pq * 8;
                ra_h[i] = (ga < M) ? *(const uint4*)(Ah + ao) : make_uint4(0, 0, 0, 0);
                size_t bo = (size_t)(n0 + r) * 512 + kb + pq * 8;
                rb_h[i] = *(const uint4*)(Bh + bo);
                rb_l[i] = *(const uint4*)(Bl + bo);
            }
        }

#pragma unroll
        for (int step = 0; step < 2; step++) {
            const int k0 = step * 16;
            uint32_t aoff[2];
#pragma unroll
            for (int mt = 0; mt < 2; mt++) {
                int ar = wm * 32 + mt * 16 + (lt & 1) * 8 + lr;
                int ak = k0 + (lt >> 1) * 8;
                aoff[mt] = (uint32_t)(ar * LDB_S + ak) * 2;
            }
            uint32_t boff[4];
#pragma unroll
            for (int ntp = 0; ntp < 4; ntp++) {
                int nr = wn * 64 + ntp * 16 + (lt >> 1) * 8 + lr;
                int nk = k0 + (lt & 1) * 8;
                boff[ntp] = (uint32_t)(nr * LDB_S + nk) * 2;
            }

            uint32_t ah[2][4], bh[4][4], bl[4][4];
#pragma unroll
            for (int mt = 0; mt < 2; mt++) ldsm_x4(ah[mt], sAh + aoff[mt]);
#pragma unroll
            for (int ntp = 0; ntp < 4; ntp++) ldsm_x4(bh[ntp], sBh + boff[ntp]);
#pragma unroll
            for (int mt = 0; mt < 2; mt++)
#pragma unroll
                for (int nt = 0; nt < 8; nt++)
                    mma_bf16(acc[mt][nt], ah[mt], &bh[nt >> 1][(nt & 1) * 2]);

#pragma unroll
            for (int ntp = 0; ntp < 4; ntp++) ldsm_x4(bl[ntp], sBl + boff[ntp]);
#pragma unroll
            for (int mt = 0; mt < 2; mt++)
#pragma unroll
                for (int nt = 0; nt < 8; nt++)
                    mma_bf16(acc[mt][nt], ah[mt], &bl[nt >> 1][(nt & 1) * 2]);
        }
        __syncthreads();
    }

    if (!fuse_pool) {
        // epilogue: bias + relu; hi store to panel cols 256..511
#pragma unroll
        for (int mt = 0; mt < 2; mt++) {
            int rbase = row0 + wm * 32 + mt * 16 + g;
#pragma unroll
            for (int nt = 0; nt < 8; nt++) {
                int col = n0 + wn * 64 + nt * 8 + th * 2;
                float bx = bias[col], by = bias[col + 1];
                float2 v0 = make_float2(fmaxf(acc[mt][nt][0] + bx, 0.f),
                                        fmaxf(acc[mt][nt][1] + by, 0.f));
                float2 v1 = make_float2(fmaxf(acc[mt][nt][2] + bx, 0.f),
                                        fmaxf(acc[mt][nt][3] + by, 0.f));
                if (rbase < M) {
                    uint16_t h0 = bf_bits(v0.x), h1 = bf_bits(v0.y);
                    *(uint32_t*)(oAh + (size_t)rbase * 512 + 256 + col) =
                        (uint32_t)h0 | ((uint32_t)h1 << 16);
                }
                if (rbase + 8 < M) {
                    uint16_t h0 = bf_bits(v1.x), h1 = bf_bits(v1.y);
                    *(uint32_t*)(oAh + (size_t)(rbase + 8) * 512 + 256 + col) =
                        (uint32_t)h0 | ((uint32_t)h1 << 16);
                }
            }
        }
    } else {
        float* red = (float*)smraw;              // [128][66] = 33792B exactly
        __shared__ int sbat[128];
#pragma unroll 1
        for (int h = 0; h < 2; h++) {
            __syncthreads();
            if (tid < 128) sbat[tid] = (row0 + tid < M) ? batchp[row0 + tid] : -1;
            if (wn == h) {
#pragma unroll
                for (int mt = 0; mt < 2; mt++) {
                    int rl = wm * 32 + mt * 16 + g;
#pragma unroll
                    for (int nt = 0; nt < 8; nt++) {
                        int cl = nt * 8 + th * 2;
                        int colg = n0 + h * 64 + cl;
                        float bx = bias[colg], by = bias[colg + 1];
                        red[rl * 66 + cl]       = fmaxf(acc[mt][nt][0] + bx, 0.f);
                        red[rl * 66 + cl + 1]   = fmaxf(acc[mt][nt][1] + by, 0.f);
                        red[(rl + 8) * 66 + cl]     = fmaxf(acc[mt][nt][2] + bx, 0.f);
                        red[(rl + 8) * 66 + cl + 1] = fmaxf(acc[mt][nt][3] + by, 0.f);
                    }
                }
            }
            __syncthreads();
            int cl = tid & 63, rh = tid >> 6;
            float run = 0.f; int cur = -1;
#pragma unroll 1
            for (int r = rh * 32; r < rh * 32 + 32; r++) {
                int gb = sbat[r];
                if (gb != cur) {
                    if (cur >= 0)
                        atomicAdd(&psum[(size_t)cur * 256 + n0 + h * 64 + cl], run);
                    run = 0.f; cur = gb;
                }
                if (gb >= 0) run += red[r * 66 + cl];
            }
            if (cur >= 0)
                atomicAdd(&psum[(size_t)cur * 256 + n0 + h * 64 + cl], run);
        }
    }
}

// ---------------- finalize pooled means ----------------
__global__ void finalize_kernel() {
    int i = blockIdx.x * blockDim.x + threadIdx.x;
    if (i >= N_GRAPHS * HID) return;
    float c = (float)g_gcnt[i >> 8];
    g_pool[i] = g_pool[i] / fmaxf(c, 1.f);
}

// ---------------- fp32 GEMM (head MLP only; small) ----------------
__global__ __launch_bounds__(256, 2) void gemm_bias_act(
    const float* __restrict__ A1, int K1, const float* __restrict__ B1,
    const float* __restrict__ bias, float* __restrict__ Cc,
    int M, int Nout, int do_relu)
{
    __shared__ float As[8][132];
    __shared__ float Bs[8][128];
    int tid = threadIdx.x;
    int tx = tid & 15, ty = tid >> 4;
    int row0 = blockIdx.x * 128;
    int col0 = blockIdx.y * 128;

    unsigned long long acc[8][4];
#pragma unroll
    for (int i = 0; i < 8; i++)
#pragma unroll
        for (int j = 0; j < 4; j++) acc[i][j] = 0ull;

    int lm = tid >> 1, lk = (tid & 1) * 4;
    int bk = tid >> 5, bn = (tid & 31) * 4;

#pragma unroll 1
    for (int k0 = 0; k0 < K1; k0 += 8) {
        float4 av = make_float4(0.f, 0.f, 0.f, 0.f);
        int r = row0 + lm;
        if (r < M) av = *(const float4*)(A1 + (size_t)r * K1 + k0 + lk);
        float4 bv = *(const float4*)(B1 + (size_t)(k0 + bk) * Nout + col0 + bn);
        __syncthreads();
        As[lk + 0][lm] = av.x; As[lk + 1][lm] = av.y;
        As[lk + 2][lm] = av.z; As[lk + 3][lm] = av.w;
        *(float4*)&Bs[bk][bn] = bv;
        __syncthreads();
#pragma unroll
        for (int k = 0; k < 8; k++) {
            float4 a0 = *(const float4*)&As[k][ty * 4];
            float4 a1 = *(const float4*)&As[k][64 + ty * 4];
            float4 b0 = *(const float4*)&Bs[k][tx * 4];
            float4 b1 = *(const float4*)&Bs[k][64 + tx * 4];
            unsigned long long bp[4];
            bp[0] = pk2(b0.x, b0.y); bp[1] = pk2(b0.z, b0.w);
            bp[2] = pk2(b1.x, b1.y); bp[3] = pk2(b1.z, b1.w);
            float a[8] = {a0.x, a0.y, a0.z, a0.w, a1.x, a1.y, a1.z, a1.w};
#pragma unroll
            for (int i = 0; i < 8; i++) {
                unsigned long long ai = dup2(a[i]);
                fma2(acc[i][0], ai, bp[0]);
                fma2(acc[i][1], ai, bp[1]);
                fma2(acc[i][2], ai, bp[2]);
                fma2(acc[i][3], ai, bp[3]);
            }
        }
    }
#pragma unroll
    for (int i = 0; i < 8; i++) {
        int r = row0 + ((i < 4) ? ty * 4 + i : 64 + ty * 4 + (i - 4));
        if (r >= M) continue;
#pragma unroll
        for (int j = 0; j < 4; j++) {
            int c = col0 + ((j < 2) ? tx * 4 + j * 2 : 64 + tx * 4 + (j - 2) * 2);
            float2 v = upk2(acc[i][j]);
            v.x += bias[c]; v.y += bias[c + 1];
            if (do_relu) { v.x = fmaxf(v.x, 0.f); v.y = fmaxf(v.y, 0.f); }
            *(float2*)(Cc + (size_t)r * Nout + c) = v;
        }
    }
}

// ---------------- launch ----------------
extern "C" void kernel_launch(void* const* d_in, const int* in_sizes, int n_in,
                              void* d_out, int out_size) {
    const float* x   = (const float*)d_in[0];
    const int*   ei  = (const int*)d_in[1];
    const int*   src = ei;
    const int*   dst = ei + N_EDGES;
    const int* batch = (const int*)d_in[2];
    const float* W1l = (const float*)d_in[3];
    const float* b1  = (const float*)d_in[4];
    const float* W1r = (const float*)d_in[5];
    const float* W2l = (const float*)d_in[6];
    const float* b2  = (const float*)d_in[7];
    const float* W2r = (const float*)d_in[8];
    const float* W3  = (const float*)d_in[9];
    const float* b3  = (const float*)d_in[10];
    const float* W4  = (const float*)d_in[11];
    const float* b4  = (const float*)d_in[12];
    float* out = (float*)d_out;

    void *p_pool, *p_hidden, *p_Ah, *p_B1h, *p_B1l, *p_B2h, *p_B2l;
    cudaGetSymbolAddress(&p_pool, g_pool);
    cudaGetSymbolAddress(&p_hidden, g_hidden);
    cudaGetSymbolAddress(&p_Ah, g_Ah);
    cudaGetSymbolAddress(&p_B1h, g_B1h);
    cudaGetSymbolAddress(&p_B1l, g_B1l);
    cudaGetSymbolAddress(&p_B2h, g_B2h);
    cudaGetSymbolAddress(&p_B2l, g_B2l);
    float* pooled = (float*)p_pool;
    float* hidden = (float*)p_hidden;
    uint16_t* Ah = (uint16_t*)p_Ah;
    uint16_t* B1h = (uint16_t*)p_B1h;
    uint16_t* B1l = (uint16_t*)p_B1l;
    uint16_t* B2h = (uint16_t*)p_B2h;
    uint16_t* B2l = (uint16_t*)p_B2l;

    static cudaStream_t s_aux = nullptr;
    static cudaEvent_t ev_fork = nullptr, ev_join = nullptr;
    if (!s_aux) {
        cudaStreamCreateWithFlags(&s_aux, cudaStreamNonBlocking);
        cudaEventCreateWithFlags(&ev_fork, cudaEventDisableTiming);
        cudaEventCreateWithFlags(&ev_join, cudaEventDisableTiming);
    }

    const int TB = 256;
    const dim3 ggrid((N_NODES + 127) / 128, 2);
    const int NSCAN = (N_NODES + 1023) / 1024;

    // ---- fork: weight/x conversions on aux stream ----
    cudaEventRecord(ev_fork, 0);
    cudaStreamWaitEvent(s_aux, ev_fork, 0);
    xsplit_kernel<<<(N_NODES * 32 + TB - 1) / TB, TB, 0, s_aux>>>(x, Ah);
    wsplit_kernel<<<(256 * 128 + TB - 1) / TB, TB, 0, s_aux>>>(W1l, 128, 0, B1h, B1l);
    wsplit_kernel<<<(256 * 128 + TB - 1) / TB, TB, 0, s_aux>>>(W1r, 128, 128, B1h, B1l);
    wsplit_kernel<<<(256 * 256 + TB - 1) / TB, TB, 0, s_aux>>>(W2l, 256, 0, B2h, B2l);
    wsplit_kernel<<<(256 * 256 + TB - 1) / TB, TB, 0, s_aux>>>(W2r, 256, 256, B2h, B2l);
    cudaEventRecord(ev_join, s_aux);

    // ---- main stream: CSR build + zero pooled sums ----
    zero_kernel<<<(N_GRAPHS * HID + TB - 1) / TB, TB>>>();
    hist_kernel<<<(N_EDGES + TB - 1) / TB, TB>>>(dst, batch);
    scan1_kernel<<<NSCAN, 1024>>>();
    scan2_kernel<<<1, 128>>>(NSCAN);
    scan3_kernel<<<NSCAN, 1024>>>();
    scatter_kernel<<<(N_EDGES + TB - 1) / TB, TB>>>(src, dst);

    // join before agg1 (needs x-hi panel)
    cudaStreamWaitEvent(0, ev_join, 0);

    // Layer 1: agg over hi-x panel (cols 128..255) -> cols 0..127; gemm1 K=256
    agg1_split_kernel<<<(N_NODES * 32 + TB - 1) / TB, TB>>>(Ah, Ah);
    hgemm_kernel<<<ggrid, 256>>>(Ah, B1h, B1l, 256, b1, Ah, N_NODES,
                                 nullptr, nullptr, 0);

    // Layer 2: agg over hi-h1 panel (cols 256..511) -> cols 0..255; fused-pool GEMM K=512
    agg2_split_kernel<<<(N_NODES * 32 + TB - 1) / TB, TB>>>(Ah, Ah);
    hgemm_kernel<<<ggrid, 256>>>(Ah, B2h, B2l, 512, b2, nullptr, N_NODES,
                                 batch, pooled, 1);

    // pooled means + MLP head
    finalize_kernel<<<(N_GRAPHS * HID + TB - 1) / TB, TB>>>();
    {
        dim3 grid((N_GRAPHS + 127) / 128, HID / 128);
        gemm_bias_act<<<grid, 256>>>(pooled, HID, W3, b3, hidden, N_GRAPHS, HID, 1);
    }
    {
        dim3 grid((N_GRAPHS + 127) / 128, OUT_CH / 128);
        gemm_bias_act<<<grid, 256>>>(hidden, HID, W4, b4, out, N_GRAPHS, OUT_CH, 0);
    }
}

// round 14
// speedup vs baseline: 1.8407x; 1.1504x over previous
#include <cuda_runtime.h>
#include <cuda_fp16.h>
#include <cstdint>

#define N_NODES  100000
#define N_EDGES  1600000
#define IN_CH    128
#define HID      256
#define OUT_CH   128
#define N_GRAPHS 2048

// ---------------- scratch (device globals: no allocation allowed) ----------------
__device__ int   g_deg[N_NODES];
__device__ int   g_fill[N_NODES];
__device__ int   g_rowptr[N_NODES + 1];
__device__ int   g_col[N_EDGES];
__device__ int   g_part[128];
__device__ int   g_part2[128];
__device__ int   g_gcnt[N_GRAPHS];
__device__ uint16_t g_A [(size_t)N_NODES * 512];     // fp16 A panel (stride 512)
__device__ uint16_t g_B1[256 * 512];                 // fp16 B panels (n-major, stride 512)
__device__ uint16_t g_B2[256 * 512];
__device__ float g_pool  [N_GRAPHS * HID];
__device__ float g_hidden[N_GRAPHS * HID];

// ---------------- helpers ----------------
__device__ __forceinline__ uint16_t f16_bits(float v) {
    __half h = __float2half_rn(v);
    return *(uint16_t*)&h;
}
__device__ __forceinline__ uint32_t smem_u32(const void* p) {
    uint32_t a;
    asm("{ .reg .u64 t; cvta.to.shared.u64 t, %1; cvt.u32.u64 %0, t; }" : "=r"(a) : "l"(p));
    return a;
}

// packed f32x2 helpers (head MLP GEMM)
__device__ __forceinline__ void fma2(unsigned long long& c, unsigned long long a, unsigned long long b) {
    asm("fma.rn.f32x2 %0, %1, %2, %3;" : "=l"(c) : "l"(a), "l"(b), "l"(c));
}
__device__ __forceinline__ unsigned long long pk2(float lo, float hi) {
    unsigned long long r; asm("mov.b64 %0, {%1, %2};" : "=l"(r) : "f"(lo), "f"(hi)); return r;
}
__device__ __forceinline__ unsigned long long dup2(float x) {
    unsigned long long r; asm("mov.b64 %0, {%1, %1};" : "=l"(r) : "f"(x)); return r;
}
__device__ __forceinline__ float2 upk2(unsigned long long v) {
    float2 r; asm("mov.b64 {%0, %1}, %2;" : "=f"(r.x), "=f"(r.y) : "l"(v)); return r;
}

// ---------------- CSR build + zero ----------------
__global__ void zero_kernel() {
    int i = blockIdx.x * blockDim.x + threadIdx.x;
    if (i < N_NODES) { g_deg[i] = 0; g_fill[i] = 0; }
    if (i < N_GRAPHS * HID) g_pool[i] = 0.f;
    if (i < N_GRAPHS) g_gcnt[i] = 0;
}
__global__ void hist_kernel(const int* __restrict__ dst, const int* __restrict__ batch) {
    int e = blockIdx.x * blockDim.x + threadIdx.x;
    if (e < N_EDGES) atomicAdd(&g_deg[dst[e]], 1);
    if (e < N_NODES) atomicAdd(&g_gcnt[batch[e]], 1);
}
__global__ void scan1_kernel() {
    __shared__ int sh[1024];
    int t = threadIdx.x;
    int i = blockIdx.x * 1024 + t;
    sh[t] = (i < N_NODES) ? g_deg[i] : 0;
    __syncthreads();
    for (int off = 512; off > 0; off >>= 1) {
        if (t < off) sh[t] += sh[t + off];
        __syncthreads();
    }
    if (t == 0) g_part[blockIdx.x] = sh[0];
}
__global__ void scan2_kernel(int nparts) {
    __shared__ int sh[128];
    int t = threadIdx.x;
    int v = (t < nparts) ? g_part[t] : 0;
    sh[t] = v;
    __syncthreads();
    for (int off = 1; off < 128; off <<= 1) {
        int nv = (t >= off) ? sh[t - off] : 0;
        __syncthreads();
        sh[t] += nv;
        __syncthreads();
    }
    if (t < nparts) g_part2[t] = sh[t] - v;
    if (t == 0) g_rowptr[N_NODES] = N_EDGES;
}
__global__ void scan3_kernel() {
    __shared__ int sh[1024];
    int t = threadIdx.x;
    int i = blockIdx.x * 1024 + t;
    int v = (i < N_NODES) ? g_deg[i] : 0;
    sh[t] = v;
    __syncthreads();
    for (int off = 1; off < 1024; off <<= 1) {
        int nv = (t >= off) ? sh[t - off] : 0;
        __syncthreads();
        sh[t] += nv;
        __syncthreads();
    }
    if (i < N_NODES) g_rowptr[i] = sh[t] - v + g_part2[blockIdx.x];
}
__global__ void scatter_kernel(const int* __restrict__ src, const int* __restrict__ dst) {
    int e = blockIdx.x * blockDim.x + threadIdx.x;
    if (e >= N_EDGES) return;
    int d = dst[e];
    int p = g_rowptr[d] + atomicAdd(&g_fill[d], 1);
    g_col[p] = src[e];
}

// ---------------- fp16 writers / readers ----------------
__device__ __forceinline__ void h_store4(uint16_t* A, size_t base,
                                         float v0, float v1, float v2, float v3) {
    uint16_t h0 = f16_bits(v0), h1 = f16_bits(v1), h2 = f16_bits(v2), h3 = f16_bits(v3);
    *(uint2*)(A + base) = make_uint2((uint32_t)h0 | ((uint32_t)h1 << 16),
                                     (uint32_t)h2 | ((uint32_t)h3 << 16));
}
__device__ __forceinline__ void add4h(float* acc, uint2 h) {
    const uint32_t* hp = (const uint32_t*)&h;
#pragma unroll
    for (int i = 0; i < 2; i++) {
        __half2 hb = *(__half2*)&hp[i];
        float2 hf = __half22float2(hb);
        acc[i * 2]     += hf.x;
        acc[i * 2 + 1] += hf.y;
    }
}
__device__ __forceinline__ void add8h(float* acc, uint4 h) {
    const uint32_t* hp = (const uint32_t*)&h;
#pragma unroll
    for (int i = 0; i < 4; i++) {
        __half2 hb = *(__half2*)&hp[i];
        float2 hf = __half22float2(hb);
        acc[i * 2]     += hf.x;
        acc[i * 2 + 1] += hf.y;
    }
}

// layer-1 mean aggregation: gathers fp16 x (panel cols 128..255), writes cols 0..127
__global__ void agg1_kernel(const uint16_t* __restrict__ Ap, uint16_t* __restrict__ A) {
    int w = (blockIdx.x * blockDim.x + threadIdx.x) >> 5;
    int lane = threadIdx.x & 31;
    if (w >= N_NODES) return;
    int beg = g_rowptr[w], end = g_rowptr[w + 1];
    float acc[4];
#pragma unroll
    for (int i = 0; i < 4; i++) acc[i] = 0.f;
    int j = beg;
    for (; j + 1 < end; j += 2) {
        int s0 = g_col[j], s1 = g_col[j + 1];
        uint2 h0 = *(const uint2*)(Ap + (size_t)s0 * 512 + 128 + lane * 4);
        uint2 h1 = *(const uint2*)(Ap + (size_t)s1 * 512 + 128 + lane * 4);
        add4h(acc, h0);
        add4h(acc, h1);
    }
    if (j < end) {
        uint2 h0 = *(const uint2*)(Ap + (size_t)g_col[j] * 512 + 128 + lane * 4);
        add4h(acc, h0);
    }
    float inv = (end > beg) ? 1.f / (float)(end - beg) : 0.f;
    h_store4(A, (size_t)w * 512 + (size_t)lane * 4,
             acc[0] * inv, acc[1] * inv, acc[2] * inv, acc[3] * inv);
}

// layer-2 mean aggregation: gathers fp16 h1 (panel cols 256..511), writes cols 0..255
__global__ void agg2_kernel(const uint16_t* __restrict__ Ap, uint16_t* __restrict__ A) {
    int w = (blockIdx.x * blockDim.x + threadIdx.x) >> 5;
    int lane = threadIdx.x & 31;
    if (w >= N_NODES) return;
    int beg = g_rowptr[w], end = g_rowptr[w + 1];
    float acc[8];
#pragma unroll
    for (int i = 0; i < 8; i++) acc[i] = 0.f;
    int j = beg;
    for (; j + 1 < end; j += 2) {
        int s0 = g_col[j], s1 = g_col[j + 1];
        uint4 h0 = *(const uint4*)(Ap + (size_t)s0 * 512 + 256 + lane * 8);
        uint4 h1 = *(const uint4*)(Ap + (size_t)s1 * 512 + 256 + lane * 8);
        add8h(acc, h0);
        add8h(acc, h1);
    }
    if (j < end) {
        uint4 h0 = *(const uint4*)(Ap + (size_t)g_col[j] * 512 + 256 + lane * 8);
        add8h(acc, h0);
    }
    float inv = (end > beg) ? 1.f / (float)(end - beg) : 0.f;
    size_t base = (size_t)w * 512 + (size_t)lane * 8;
    h_store4(A, base,     acc[0] * inv, acc[1] * inv, acc[2] * inv, acc[3] * inv);
    h_store4(A, base + 4, acc[4] * inv, acc[5] * inv, acc[6] * inv, acc[7] * inv);
}

// convert x (fp32 [N,128]) into A panel cols 128..255
__global__ void xconv_kernel(const float* __restrict__ x, uint16_t* __restrict__ A) {
    int idx = blockIdx.x * blockDim.x + threadIdx.x;
    if (idx >= N_NODES * 32) return;
    int row = idx >> 5, q = idx & 31;
    float4 v = ((const float4*)x)[idx];
    h_store4(A, (size_t)row * 512 + 128 + (size_t)q * 4, v.x, v.y, v.z, v.w);
}

// transpose + convert weight W[Kw,256] into B panel
__global__ void wconv_kernel(const float* __restrict__ W, int Kw, int cofs,
                             uint16_t* __restrict__ B) {
    int idx = blockIdx.x * blockDim.x + threadIdx.x;
    if (idx >= 256 * Kw) return;
    int n = idx / Kw, k = idx - n * Kw;
    B[(size_t)n * 512 + cofs + k] = f16_bits(W[(size_t)k * 256 + n]);
}

// ---------------- single-pass fp16 HMMA GEMM: D = A * B^T ----------------
#define LDB_S 40

__device__ __forceinline__ void mma_f16(float* c, const uint32_t* a, const uint32_t* b) {
    asm volatile(
        "mma.sync.aligned.m16n8k16.row.col.f32.f16.f16.f32 "
        "{%0,%1,%2,%3}, {%4,%5,%6,%7}, {%8,%9}, {%0,%1,%2,%3};"
        : "+f"(c[0]), "+f"(c[1]), "+f"(c[2]), "+f"(c[3])
        : "r"(a[0]), "r"(a[1]), "r"(a[2]), "r"(a[3]), "r"(b[0]), "r"(b[1]));
}
__device__ __forceinline__ void ldsm_x4(uint32_t* r, uint32_t addr) {
    asm volatile("ldmatrix.sync.aligned.m8n8.x4.shared.b16 {%0,%1,%2,%3}, [%4];"
                 : "=r"(r[0]), "=r"(r[1]), "=r"(r[2]), "=r"(r[3]) : "r"(addr));
}

__global__ __launch_bounds__(256, 1) void hgemm_kernel(
    const uint16_t* __restrict__ A, const uint16_t* __restrict__ B,
    int K, const float* __restrict__ bias,
    uint16_t* __restrict__ oA,
    int M, const int* __restrict__ batchp, float* __restrict__ psum, int fuse_pool)
{
    __shared__ __align__(16) uint8_t smraw[33792];   // As 10240 + Bs 10240; pool scratch reuse
    uint16_t* As = (uint16_t*)(smraw);
    uint16_t* Bs = (uint16_t*)(smraw + 10240);

    const int tid = threadIdx.x;
    const int lane = tid & 31, wid = tid >> 5;
    const int wm = wid & 3, wn = wid >> 2;
    const int g = lane >> 2, th = lane & 3;
    const int row0 = blockIdx.x * 128;
    const int n0 = blockIdx.y * 128;

    const uint32_t sA = smem_u32(smraw);
    const uint32_t sB = sA + 10240;

    const int nch = K >> 5;

    float acc[2][8][4];
#pragma unroll
    for (int mt = 0; mt < 2; mt++)
#pragma unroll
        for (int nt = 0; nt < 8; nt++)
#pragma unroll
            for (int r = 0; r < 4; r++) acc[mt][nt][r] = 0.f;

    const int lt = lane >> 3, lr = lane & 7;
    const int pr = tid >> 2, pq = tid & 3;

    uint4 ra[2], rb[2];
    {
#pragma unroll
        for (int i = 0; i < 2; i++) {
            int r = pr + i * 64;
            int ga = row0 + r;
            size_t ao = (size_t)ga * 512 + pq * 8;
            ra[i] = (ga < M) ? *(const uint4*)(A + ao) : make_uint4(0, 0, 0, 0);
            rb[i] = *(const uint4*)(B + (size_t)(n0 + r) * 512 + pq * 8);
        }
    }

#pragma unroll 1
    for (int c = 0; c < nch; c++) {
#pragma unroll
        for (int i = 0; i < 2; i++) {
            int r = pr + i * 64;
            int so = r * LDB_S + pq * 8;
            *(uint4*)&As[so] = ra[i];
            *(uint4*)&Bs[so] = rb[i];
        }
        __syncthreads();

        if (c + 1 < nch) {
            int kb = (c + 1) * 32;
#pragma unroll
            for (int i = 0; i < 2; i++) {
                int r = pr + i * 64;
                int ga = row0 + r;
                size_t ao = (size_t)ga * 512 + kb + pq * 8;
                ra[i] = (ga < M) ? *(const uint4*)(A + ao) : make_uint4(0, 0, 0, 0);
                rb[i] = *(const uint4*)(B + (size_t)(n0 + r) * 512 + kb + pq * 8);
            }
        }

#pragma unroll
        for (int step = 0; step < 2; step++) {
            const int k0 = step * 16;
            uint32_t aoff[2];
#pragma unroll
            for (int mt = 0; mt < 2; mt++) {
                int ar = wm * 32 + mt * 16 + (lt & 1) * 8 + lr;
                int ak = k0 + (lt >> 1) * 8;
                aoff[mt] = (uint32_t)(ar * LDB_S + ak) * 2;
            }
            uint32_t boff[4];
#pragma unroll
            for (int ntp = 0; ntp < 4; ntp++) {
                int nr = wn * 64 + ntp * 16 + (lt >> 1) * 8 + lr;
                int nk = k0 + (lt & 1) * 8;
                boff[ntp] = (uint32_t)(nr * LDB_S + nk) * 2;
            }

            uint32_t ah[2][4], bh[4][4];
#pragma unroll
            for (int mt = 0; mt < 2; mt++) ldsm_x4(ah[mt], sA + aoff[mt]);
#pragma unroll
            for (int ntp = 0; ntp < 4; ntp++) ldsm_x4(bh[ntp], sB + boff[ntp]);
#pragma unroll
            for (int mt = 0; mt < 2; mt++)
#pragma unroll
                for (int nt = 0; nt < 8; nt++)
                    mma_f16(acc[mt][nt], ah[mt], &bh[nt >> 1][(nt & 1) * 2]);
        }
        __syncthreads();
    }

    if (!fuse_pool) {
        // epilogue: bias + relu; fp16 store to panel cols 256..511
#pragma unroll
        for (int mt = 0; mt < 2; mt++) {
            int rbase = row0 + wm * 32 + mt * 16 + g;
#pragma unroll
            for (int nt = 0; nt < 8; nt++) {
                int col = n0 + wn * 64 + nt * 8 + th * 2;
                float bx = bias[col], by = bias[col + 1];
                float2 v0 = make_float2(fmaxf(acc[mt][nt][0] + bx, 0.f),
                                        fmaxf(acc[mt][nt][1] + by, 0.f));
                float2 v1 = make_float2(fmaxf(acc[mt][nt][2] + bx, 0.f),
                                        fmaxf(acc[mt][nt][3] + by, 0.f));
                if (rbase < M) {
                    uint16_t h0 = f16_bits(v0.x), h1 = f16_bits(v0.y);
                    *(uint32_t*)(oA + (size_t)rbase * 512 + 256 + col) =
                        (uint32_t)h0 | ((uint32_t)h1 << 16);
                }
                if (rbase + 8 < M) {
                    uint16_t h0 = f16_bits(v1.x), h1 = f16_bits(v1.y);
                    *(uint32_t*)(oA + (size_t)(rbase + 8) * 512 + 256 + col) =
                        (uint32_t)h0 | ((uint32_t)h1 << 16);
                }
            }
        }
    } else {
        float* red = (float*)smraw;              // [128][66] = 33792B exactly
        __shared__ int sbat[128];
#pragma unroll 1
        for (int h = 0; h < 2; h++) {
            __syncthreads();
            if (tid < 128) sbat[tid] = (row0 + tid < M) ? batchp[row0 + tid] : -1;
            if (wn == h) {
#pragma unroll
                for (int mt = 0; mt < 2; mt++) {
                    int rl = wm * 32 + mt * 16 + g;
#pragma unroll
                    for (int nt = 0; nt < 8; nt++) {
                        int cl = nt * 8 + th * 2;
                        int colg = n0 + h * 64 + cl;
                        float bx = bias[colg], by = bias[colg + 1];
                        red[rl * 66 + cl]       = fmaxf(acc[mt][nt][0] + bx, 0.f);
                        red[rl * 66 + cl + 1]   = fmaxf(acc[mt][nt][1] + by, 0.f);
                        red[(rl + 8) * 66 + cl]     = fmaxf(acc[mt][nt][2] + bx, 0.f);
                        red[(rl + 8) * 66 + cl + 1] = fmaxf(acc[mt][nt][3] + by, 0.f);
                    }
                }
            }
            __syncthreads();
            int cl = tid & 63, rh = tid >> 6;
            float run = 0.f; int cur = -1;
#pragma unroll 1
            for (int r = rh * 32; r < rh * 32 + 32; r++) {
                int gb = sbat[r];
                if (gb != cur) {
                    if (cur >= 0)
                        atomicAdd(&psum[(size_t)cur * 256 + n0 + h * 64 + cl], run);
                    run = 0.f; cur = gb;
                }
                if (gb >= 0) run += red[r * 66 + cl];
            }
            if (cur >= 0)
                atomicAdd(&psum[(size_t)cur * 256 + n0 + h * 64 + cl], run);
        }
    }
}

// ---------------- finalize pooled means ----------------
__global__ void finalize_kernel() {
    int i = blockIdx.x * blockDim.x + threadIdx.x;
    if (i >= N_GRAPHS * HID) return;
    float c = (float)g_gcnt[i >> 8];
    g_pool[i] = g_pool[i] / fmaxf(c, 1.f);
}

// ---------------- fp32 GEMM (head MLP only; small) ----------------
__global__ __launch_bounds__(256, 2) void gemm_bias_act(
    const float* __restrict__ A1, int K1, const float* __restrict__ B1,
    const float* __restrict__ bias, float* __restrict__ Cc,
    int M, int Nout, int do_relu)
{
    __shared__ float As[8][132];
    __shared__ float Bs[8][128];
    int tid = threadIdx.x;
    int tx = tid & 15, ty = tid >> 4;
    int row0 = blockIdx.x * 128;
    int col0 = blockIdx.y * 128;

    unsigned long long acc[8][4];
#pragma unroll
    for (int i = 0; i < 8; i++)
#pragma unroll
        for (int j = 0; j < 4; j++) acc[i][j] = 0ull;

    int lm = tid >> 1, lk = (tid & 1) * 4;
    int bk = tid >> 5, bn = (tid & 31) * 4;

#pragma unroll 1
    for (int k0 = 0; k0 < K1; k0 += 8) {
        float4 av = make_float4(0.f, 0.f, 0.f, 0.f);
        int r = row0 + lm;
        if (r < M) av = *(const float4*)(A1 + (size_t)r * K1 + k0 + lk);
        float4 bv = *(const float4*)(B1 + (size_t)(k0 + bk) * Nout + col0 + bn);
        __syncthreads();
        As[lk + 0][lm] = av.x; As[lk + 1][lm] = av.y;
        As[lk + 2][lm] = av.z; As[lk + 3][lm] = av.w;
        *(float4*)&Bs[bk][bn] = bv;
        __syncthreads();
#pragma unroll
        for (int k = 0; k < 8; k++) {
            float4 a0 = *(const float4*)&As[k][ty * 4];
            float4 a1 = *(const float4*)&As[k][64 + ty * 4];
            float4 b0 = *(const float4*)&Bs[k][tx * 4];
            float4 b1 = *(const float4*)&Bs[k][64 + tx * 4];
            unsigned long long bp[4];
            bp[0] = pk2(b0.x, b0.y); bp[1] = pk2(b0.z, b0.w);
            bp[2] = pk2(b1.x, b1.y); bp[3] = pk2(b1.z, b1.w);
            float a[8] = {a0.x, a0.y, a0.z, a0.w, a1.x, a1.y, a1.z, a1.w};
#pragma unroll
            for (int i = 0; i < 8; i++) {
                unsigned long long ai = dup2(a[i]);
                fma2(acc[i][0], ai, bp[0]);
                fma2(acc[i][1], ai, bp[1]);
                fma2(acc[i][2], ai, bp[2]);
                fma2(acc[i][3], ai, bp[3]);
            }
        }
    }
#pragma unroll
    for (int i = 0; i < 8; i++) {
        int r = row0 + ((i < 4) ? ty * 4 + i : 64 + ty * 4 + (i - 4));
        if (r >= M) continue;
#pragma unroll
        for (int j = 0; j < 4; j++) {
            int c = col0 + ((j < 2) ? tx * 4 + j * 2 : 64 + tx * 4 + (j - 2) * 2);
            float2 v = upk2(acc[i][j]);
            v.x += bias[c]; v.y += bias[c + 1];
            if (do_relu) { v.x = fmaxf(v.x, 0.f); v.y = fmaxf(v.y, 0.f); }
            *(float2*)(Cc + (size_t)r * Nout + c) = v;
        }
    }
}

// ---------------- launch ----------------
extern "C" void kernel_launch(void* const* d_in, const int* in_sizes, int n_in,
                              void* d_out, int out_size) {
    const float* x   = (const float*)d_in[0];
    const int*   ei  = (const int*)d_in[1];
    const int*   src = ei;
    const int*   dst = ei + N_EDGES;
    const int* batch = (const int*)d_in[2];
    const float* W1l = (const float*)d_in[3];
    const float* b1  = (const float*)d_in[4];
    const float* W1r = (const float*)d_in[5];
    const float* W2l = (const float*)d_in[6];
    const float* b2  = (const float*)d_in[7];
    const float* W2r = (const float*)d_in[8];
    const float* W3  = (const float*)d_in[9];
    const float* b3  = (const float*)d_in[10];
    const float* W4  = (const float*)d_in[11];
    const float* b4  = (const float*)d_in[12];
    float* out = (float*)d_out;

    void *p_pool, *p_hidden, *p_A, *p_B1, *p_B2;
    cudaGetSymbolAddress(&p_pool, g_pool);
    cudaGetSymbolAddress(&p_hidden, g_hidden);
    cudaGetSymbolAddress(&p_A, g_A);
    cudaGetSymbolAddress(&p_B1, g_B1);
    cudaGetSymbolAddress(&p_B2, g_B2);
    float* pooled = (float*)p_pool;
    float* hidden = (float*)p_hidden;
    uint16_t* A  = (uint16_t*)p_A;
    uint16_t* B1 = (uint16_t*)p_B1;
    uint16_t* B2 = (uint16_t*)p_B2;

    static cudaStream_t s_aux = nullptr;
    static cudaEvent_t ev_fork = nullptr, ev_join = nullptr;
    if (!s_aux) {
        cudaStreamCreateWithFlags(&s_aux, cudaStreamNonBlocking);
        cudaEventCreateWithFlags(&ev_fork, cudaEventDisableTiming);
        cudaEventCreateWithFlags(&ev_join, cudaEventDisableTiming);
    }

    const int TB = 256;
    const dim3 ggrid((N_NODES + 127) / 128, 2);
    const int NSCAN = (N_NODES + 1023) / 1024;

    // ---- fork: weight/x conversions on aux stream ----
    cudaEventRecord(ev_fork, 0);
    cudaStreamWaitEvent(s_aux, ev_fork, 0);
    xconv_kernel<<<(N_NODES * 32 + TB - 1) / TB, TB, 0, s_aux>>>(x, A);
    wconv_kernel<<<(256 * 128 + TB - 1) / TB, TB, 0, s_aux>>>(W1l, 128, 0, B1);
    wconv_kernel<<<(256 * 128 + TB - 1) / TB, TB, 0, s_aux>>>(W1r, 128, 128, B1);
    wconv_kernel<<<(256 * 256 + TB - 1) / TB, TB, 0, s_aux>>>(W2l, 256, 0, B2);
    wconv_kernel<<<(256 * 256 + TB - 1) / TB, TB, 0, s_aux>>>(W2r, 256, 256, B2);
    cudaEventRecord(ev_join, s_aux);

    // ---- main stream: CSR build + zero pooled sums ----
    zero_kernel<<<(N_GRAPHS * HID + TB - 1) / TB, TB>>>();
    hist_kernel<<<(N_EDGES + TB - 1) / TB, TB>>>(dst, batch);
    scan1_kernel<<<NSCAN, 1024>>>();
    scan2_kernel<<<1, 128>>>(NSCAN);
    scan3_kernel<<<NSCAN, 1024>>>();
    scatter_kernel<<<(N_EDGES + TB - 1) / TB, TB>>>(src, dst);

    // join before agg1 (needs x fp16 panel)
    cudaStreamWaitEvent(0, ev_join, 0);

    // Layer 1: agg over fp16-x panel (cols 128..255) -> cols 0..127; gemm1 K=256
    agg1_kernel<<<(N_NODES * 32 + TB - 1) / TB, TB>>>(A, A);
    hgemm_kernel<<<ggrid, 256>>>(A, B1, 256, b1, A, N_NODES, nullptr, nullptr, 0);

    // Layer 2: agg over fp16-h1 panel (cols 256..511) -> cols 0..255; fused-pool GEMM K=512
    agg2_kernel<<<(N_NODES * 32 + TB - 1) / TB, TB>>>(A, A);
    hgemm_kernel<<<ggrid, 256>>>(A, B2, 512, b2, nullptr, N_NODES, batch, pooled, 1);

    // pooled means + MLP head (fp32)
    finalize_kernel<<<(N_GRAPHS * HID + TB - 1) / TB, TB>>>();
    {
        dim3 grid((N_GRAPHS + 127) / 128, HID / 128);
        gemm_bias_act<<<grid, 256>>>(pooled, HID, W3, b3, hidden, N_GRAPHS, HID, 1);
    }
    {
        dim3 grid((N_GRAPHS + 127) / 128, OUT_CH / 128);
        gemm_bias_act<<<grid, 256>>>(hidden, HID, W4, b4, out, N_GRAPHS, OUT_CH, 0);
    }
}

// round 15
// speedup vs baseline: 2.1032x; 1.1426x over previous
#include <cuda_runtime.h>
#include <cuda_fp16.h>
#include <cstdint>

#define N_NODES  100000
#define N_EDGES  1600000
#define IN_CH    128
#define HID      256
#define OUT_CH   128
#define N_GRAPHS 2048

// ---------------- scratch (device globals: no allocation allowed) ----------------
__device__ int   g_deg[N_NODES];
__device__ int   g_fill[N_NODES];
__device__ int   g_rowptr[N_NODES + 1];
__device__ int   g_col[N_EDGES];
__device__ int   g_part[128];
__device__ int   g_part2[128];
__device__ int   g_gcnt[N_GRAPHS];
__device__ uint16_t g_A [(size_t)N_NODES * 512];     // fp16 A panel (stride 512)
__device__ uint16_t g_B1[256 * 512];                 // fp16 B panels (n-major, stride 512)
__device__ uint16_t g_B2[256 * 512];
__device__ uint16_t g_B3[256 * 512];
__device__ uint16_t g_B4[256 * 512];                 // rows 128..255 stay zero
__device__ float g_pool[N_GRAPHS * HID];

// ---------------- helpers ----------------
__device__ __forceinline__ uint16_t f16_bits(float v) {
    __half h = __float2half_rn(v);
    return *(uint16_t*)&h;
}
__device__ __forceinline__ uint32_t smem_u32(const void* p) {
    uint32_t a;
    asm("{ .reg .u64 t; cvta.to.shared.u64 t, %1; cvt.u32.u64 %0, t; }" : "=r"(a) : "l"(p));
    return a;
}

// ---------------- CSR build + zero ----------------
__global__ void zero_kernel() {
    int i = blockIdx.x * blockDim.x + threadIdx.x;
    if (i < N_NODES) { g_deg[i] = 0; g_fill[i] = 0; }
    if (i < N_GRAPHS * HID) g_pool[i] = 0.f;
    if (i < N_GRAPHS) g_gcnt[i] = 0;
}
__global__ void hist_kernel(const int* __restrict__ dst, const int* __restrict__ batch) {
    int e = blockIdx.x * blockDim.x + threadIdx.x;
    if (e < N_EDGES) atomicAdd(&g_deg[dst[e]], 1);
    if (e < N_NODES) atomicAdd(&g_gcnt[batch[e]], 1);
}
__global__ void scan1_kernel() {
    __shared__ int sh[1024];
    int t = threadIdx.x;
    int i = blockIdx.x * 1024 + t;
    sh[t] = (i < N_NODES) ? g_deg[i] : 0;
    __syncthreads();
    for (int off = 512; off > 0; off >>= 1) {
        if (t < off) sh[t] += sh[t + off];
        __syncthreads();
    }
    if (t == 0) g_part[blockIdx.x] = sh[0];
}
__global__ void scan2_kernel(int nparts) {
    __shared__ int sh[128];
    int t = threadIdx.x;
    int v = (t < nparts) ? g_part[t] : 0;
    sh[t] = v;
    __syncthreads();
    for (int off = 1; off < 128; off <<= 1) {
        int nv = (t >= off) ? sh[t - off] : 0;
        __syncthreads();
        sh[t] += nv;
        __syncthreads();
    }
    if (t < nparts) g_part2[t] = sh[t] - v;
    if (t == 0) g_rowptr[N_NODES] = N_EDGES;
}
__global__ void scan3_kernel() {
    __shared__ int sh[1024];
    int t = threadIdx.x;
    int i = blockIdx.x * 1024 + t;
    int v = (i < N_NODES) ? g_deg[i] : 0;
    sh[t] = v;
    __syncthreads();
    for (int off = 1; off < 1024; off <<= 1) {
        int nv = (t >= off) ? sh[t - off] : 0;
        __syncthreads();
        sh[t] += nv;
        __syncthreads();
    }
    if (i < N_NODES) g_rowptr[i] = sh[t] - v + g_part2[blockIdx.x];
}
__global__ void scatter_kernel(const int* __restrict__ src, const int* __restrict__ dst) {
    int e = blockIdx.x * blockDim.x + threadIdx.x;
    if (e >= N_EDGES) return;
    int d = dst[e];
    int p = g_rowptr[d] + atomicAdd(&g_fill[d], 1);
    g_col[p] = src[e];
}

// ---------------- fp16 writers / readers ----------------
__device__ __forceinline__ void h_store4(uint16_t* A, size_t base,
                                         float v0, float v1, float v2, float v3) {
    uint16_t h0 = f16_bits(v0), h1 = f16_bits(v1), h2 = f16_bits(v2), h3 = f16_bits(v3);
    *(uint2*)(A + base) = make_uint2((uint32_t)h0 | ((uint32_t)h1 << 16),
                                     (uint32_t)h2 | ((uint32_t)h3 << 16));
}
__device__ __forceinline__ void add4h(float* acc, uint2 h) {
    const uint32_t* hp = (const uint32_t*)&h;
#pragma unroll
    for (int i = 0; i < 2; i++) {
        __half2 hb = *(__half2*)&hp[i];
        float2 hf = __half22float2(hb);
        acc[i * 2]     += hf.x;
        acc[i * 2 + 1] += hf.y;
    }
}
__device__ __forceinline__ void add8h(float* acc, uint4 h) {
    const uint32_t* hp = (const uint32_t*)&h;
#pragma unroll
    for (int i = 0; i < 4; i++) {
        __half2 hb = *(__half2*)&hp[i];
        float2 hf = __half22float2(hb);
        acc[i * 2]     += hf.x;
        acc[i * 2 + 1] += hf.y;
    }
}

// layer-1 mean aggregation: gathers fp16 x (panel cols 128..255), 4-way edge unroll
__global__ void agg1_kernel(const uint16_t* __restrict__ Ap, uint16_t* __restrict__ A) {
    int w = (blockIdx.x * blockDim.x + threadIdx.x) >> 5;
    int lane = threadIdx.x & 31;
    if (w >= N_NODES) return;
    int beg = g_rowptr[w], end = g_rowptr[w + 1];
    float acc[4];
#pragma unroll
    for (int i = 0; i < 4; i++) acc[i] = 0.f;
    int j = beg;
    for (; j + 3 < end; j += 4) {
        int s0 = g_col[j], s1 = g_col[j + 1], s2 = g_col[j + 2], s3 = g_col[j + 3];
        uint2 h0 = *(const uint2*)(Ap + (size_t)s0 * 512 + 128 + lane * 4);
        uint2 h1 = *(const uint2*)(Ap + (size_t)s1 * 512 + 128 + lane * 4);
        uint2 h2 = *(const uint2*)(Ap + (size_t)s2 * 512 + 128 + lane * 4);
        uint2 h3 = *(const uint2*)(Ap + (size_t)s3 * 512 + 128 + lane * 4);
        add4h(acc, h0); add4h(acc, h1); add4h(acc, h2); add4h(acc, h3);
    }
    for (; j < end; j++) {
        uint2 h0 = *(const uint2*)(Ap + (size_t)g_col[j] * 512 + 128 + lane * 4);
        add4h(acc, h0);
    }
    float inv = (end > beg) ? 1.f / (float)(end - beg) : 0.f;
    h_store4(A, (size_t)w * 512 + (size_t)lane * 4,
             acc[0] * inv, acc[1] * inv, acc[2] * inv, acc[3] * inv);
}

// layer-2 mean aggregation: gathers fp16 h1 (panel cols 256..511), 4-way edge unroll
__global__ void agg2_kernel(const uint16_t* __restrict__ Ap, uint16_t* __restrict__ A) {
    int w = (blockIdx.x * blockDim.x + threadIdx.x) >> 5;
    int lane = threadIdx.x & 31;
    if (w >= N_NODES) return;
    int beg = g_rowptr[w], end = g_rowptr[w + 1];
    float acc[8];
#pragma unroll
    for (int i = 0; i < 8; i++) acc[i] = 0.f;
    int j = beg;
    for (; j + 3 < end; j += 4) {
        int s0 = g_col[j], s1 = g_col[j + 1], s2 = g_col[j + 2], s3 = g_col[j + 3];
        uint4 h0 = *(const uint4*)(Ap + (size_t)s0 * 512 + 256 + lane * 8);
        uint4 h1 = *(const uint4*)(Ap + (size_t)s1 * 512 + 256 + lane * 8);
        uint4 h2 = *(const uint4*)(Ap + (size_t)s2 * 512 + 256 + lane * 8);
        uint4 h3 = *(const uint4*)(Ap + (size_t)s3 * 512 + 256 + lane * 8);
        add8h(acc, h0); add8h(acc, h1); add8h(acc, h2); add8h(acc, h3);
    }
    for (; j < end; j++) {
        uint4 h0 = *(const uint4*)(Ap + (size_t)g_col[j] * 512 + 256 + lane * 8);
        add8h(acc, h0);
    }
    float inv = (end > beg) ? 1.f / (float)(end - beg) : 0.f;
    size_t base = (size_t)w * 512 + (size_t)lane * 8;
    h_store4(A, base,     acc[0] * inv, acc[1] * inv, acc[2] * inv, acc[3] * inv);
    h_store4(A, base + 4, acc[4] * inv, acc[5] * inv, acc[6] * inv, acc[7] * inv);
}

// convert x (fp32 [N,128]) into A panel cols 128..255
__global__ void xconv_kernel(const float* __restrict__ x, uint16_t* __restrict__ A) {
    int idx = blockIdx.x * blockDim.x + threadIdx.x;
    if (idx >= N_NODES * 32) return;
    int row = idx >> 5, q = idx & 31;
    float4 v = ((const float4*)x)[idx];
    h_store4(A, (size_t)row * 512 + 128 + (size_t)q * 4, v.x, v.y, v.z, v.w);
}

// transpose + convert weight W[Kw,Nout] into B panel rows n<Nout
__global__ void wconv_kernel(const float* __restrict__ W, int Kw, int Nout, int cofs,
                             uint16_t* __restrict__ B) {
    int idx = blockIdx.x * blockDim.x + threadIdx.x;
    if (idx >= Nout * Kw) return;
    int n = idx / Kw, k = idx - n * Kw;
    B[(size_t)n * 512 + cofs + k] = f16_bits(W[(size_t)k * Nout + n]);
}

// ---------------- single-pass fp16 HMMA GEMM: D = A * B^T ----------------
#define LDB_S 40

__device__ __forceinline__ void mma_f16(float* c, const uint32_t* a, const uint32_t* b) {
    asm volatile(
        "mma.sync.aligned.m16n8k16.row.col.f32.f16.f16.f32 "
        "{%0,%1,%2,%3}, {%4,%5,%6,%7}, {%8,%9}, {%0,%1,%2,%3};"
        : "+f"(c[0]), "+f"(c[1]), "+f"(c[2]), "+f"(c[3])
        : "r"(a[0]), "r"(a[1]), "r"(a[2]), "r"(a[3]), "r"(b[0]), "r"(b[1]));
}
__device__ __forceinline__ void ldsm_x4(uint32_t* r, uint32_t addr) {
    asm volatile("ldmatrix.sync.aligned.m8n8.x4.shared.b16 {%0,%1,%2,%3}, [%4];"
                 : "=r"(r[0]), "=r"(r[1]), "=r"(r[2]), "=r"(r[3]) : "r"(addr));
}

__global__ __launch_bounds__(256, 1) void hgemm_kernel(
    const uint16_t* __restrict__ A, const uint16_t* __restrict__ B,
    int K, const float* __restrict__ bias,
    uint16_t* __restrict__ oA,            // fp16 panel out (cols 256..511) or nullptr
    float* __restrict__ Cf, int ldc,      // fp32 out or nullptr
    int do_relu, int M,
    const int* __restrict__ batchp, float* __restrict__ psum, int fuse_pool)
{
    __shared__ __align__(16) uint8_t smraw[33792];
    uint16_t* As = (uint16_t*)(smraw);
    uint16_t* Bs = (uint16_t*)(smraw + 10240);

    const int tid = threadIdx.x;
    const int lane = tid & 31, wid = tid >> 5;
    const int wm = wid & 3, wn = wid >> 2;
    const int g = lane >> 2, th = lane & 3;
    const int row0 = blockIdx.x * 128;
    const int n0 = blockIdx.y * 128;

    const uint32_t sA = smem_u32(smraw);
    const uint32_t sB = sA + 10240;

    const int nch = K >> 5;

    float acc[2][8][4];
#pragma unroll
    for (int mt = 0; mt < 2; mt++)
#pragma unroll
        for (int nt = 0; nt < 8; nt++)
#pragma unroll
            for (int r = 0; r < 4; r++) acc[mt][nt][r] = 0.f;

    const int lt = lane >> 3, lr = lane & 7;
    const int pr = tid >> 2, pq = tid & 3;

    uint4 ra[2], rb[2];
    {
#pragma unroll
        for (int i = 0; i < 2; i++) {
            int r = pr + i * 64;
            int ga = row0 + r;
            size_t ao = (size_t)ga * 512 + pq * 8;
            ra[i] = (ga < M) ? *(const uint4*)(A + ao) : make_uint4(0, 0, 0, 0);
            rb[i] = *(const uint4*)(B + (size_t)(n0 + r) * 512 + pq * 8);
        }
    }

#pragma unroll 1
    for (int c = 0; c < nch; c++) {
#pragma unroll
        for (int i = 0; i < 2; i++) {
            int r = pr + i * 64;
            int so = r * LDB_S + pq * 8;
            *(uint4*)&As[so] = ra[i];
            *(uint4*)&Bs[so] = rb[i];
        }
        __syncthreads();

        if (c + 1 < nch) {
            int kb = (c + 1) * 32;
#pragma unroll
            for (int i = 0; i < 2; i++) {
                int r = pr + i * 64;
                int ga = row0 + r;
                size_t ao = (size_t)ga * 512 + kb + pq * 8;
                ra[i] = (ga < M) ? *(const uint4*)(A + ao) : make_uint4(0, 0, 0, 0);
                rb[i] = *(const uint4*)(B + (size_t)(n0 + r) * 512 + kb + pq * 8);
            }
        }

#pragma unroll
        for (int step = 0; step < 2; step++) {
            const int k0 = step * 16;
            uint32_t aoff[2];
#pragma unroll
            for (int mt = 0; mt < 2; mt++) {
                int ar = wm * 32 + mt * 16 + (lt & 1) * 8 + lr;
                int ak = k0 + (lt >> 1) * 8;
                aoff[mt] = (uint32_t)(ar * LDB_S + ak) * 2;
            }
            uint32_t boff[4];
#pragma unroll
            for (int ntp = 0; ntp < 4; ntp++) {
                int nr = wn * 64 + ntp * 16 + (lt >> 1) * 8 + lr;
                int nk = k0 + (lt & 1) * 8;
                boff[ntp] = (uint32_t)(nr * LDB_S + nk) * 2;
            }

            uint32_t ah[2][4], bh[4][4];
#pragma unroll
            for (int mt = 0; mt < 2; mt++) ldsm_x4(ah[mt], sA + aoff[mt]);
#pragma unroll
            for (int ntp = 0; ntp < 4; ntp++) ldsm_x4(bh[ntp], sB + boff[ntp]);
#pragma unroll
            for (int mt = 0; mt < 2; mt++)
#pragma unroll
                for (int nt = 0; nt < 8; nt++)
                    mma_f16(acc[mt][nt], ah[mt], &bh[nt >> 1][(nt & 1) * 2]);
        }
        __syncthreads();
    }

    if (!fuse_pool) {
#pragma unroll
        for (int mt = 0; mt < 2; mt++) {
            int rbase = row0 + wm * 32 + mt * 16 + g;
#pragma unroll
            for (int nt = 0; nt < 8; nt++) {
                int col = n0 + wn * 64 + nt * 8 + th * 2;
                float bx = bias[col], by = bias[col + 1];
                float2 v0 = make_float2(acc[mt][nt][0] + bx, acc[mt][nt][1] + by);
                float2 v1 = make_float2(acc[mt][nt][2] + bx, acc[mt][nt][3] + by);
                if (do_relu) {
                    v0.x = fmaxf(v0.x, 0.f); v0.y = fmaxf(v0.y, 0.f);
                    v1.x = fmaxf(v1.x, 0.f); v1.y = fmaxf(v1.y, 0.f);
                }
                if (rbase < M) {
                    if (oA) {
                        uint16_t h0 = f16_bits(v0.x), h1 = f16_bits(v0.y);
                        *(uint32_t*)(oA + (size_t)rbase * 512 + 256 + col) =
                            (uint32_t)h0 | ((uint32_t)h1 << 16);
                    }
                    if (Cf) *(float2*)(Cf + (size_t)rbase * ldc + col) = v0;
                }
                if (rbase + 8 < M) {
                    if (oA) {
                        uint16_t h0 = f16_bits(v1.x), h1 = f16_bits(v1.y);
                        *(uint32_t*)(oA + (size_t)(rbase + 8) * 512 + 256 + col) =
                            (uint32_t)h0 | ((uint32_t)h1 << 16);
                    }
                    if (Cf) *(float2*)(Cf + (size_t)(rbase + 8) * ldc + col) = v1;
                }
            }
        }
    } else {
        float* red = (float*)smraw;              // [128][66] = 33792B exactly
        __shared__ int sbat[128];
#pragma unroll 1
        for (int h = 0; h < 2; h++) {
            __syncthreads();
            if (tid < 128) sbat[tid] = (row0 + tid < M) ? batchp[row0 + tid] : -1;
            if (wn == h) {
#pragma unroll
                for (int mt = 0; mt < 2; mt++) {
                    int rl = wm * 32 + mt * 16 + g;
#pragma unroll
                    for (int nt = 0; nt < 8; nt++) {
                        int cl = nt * 8 + th * 2;
                        int colg = n0 + h * 64 + cl;
                        float bx = bias[colg], by = bias[colg + 1];
                        red[rl * 66 + cl]       = fmaxf(acc[mt][nt][0] + bx, 0.f);
                        red[rl * 66 + cl + 1]   = fmaxf(acc[mt][nt][1] + by, 0.f);
                        red[(rl + 8) * 66 + cl]     = fmaxf(acc[mt][nt][2] + bx, 0.f);
                        red[(rl + 8) * 66 + cl + 1] = fmaxf(acc[mt][nt][3] + by, 0.f);
                    }
                }
            }
            __syncthreads();
            int cl = tid & 63, rh = tid >> 6;
            float run = 0.f; int cur = -1;
#pragma unroll 1
            for (int r = rh * 32; r < rh * 32 + 32; r++) {
                int gb = sbat[r];
                if (gb != cur) {
                    if (cur >= 0)
                        atomicAdd(&psum[(size_t)cur * 256 + n0 + h * 64 + cl], run);
                    run = 0.f; cur = gb;
                }
                if (gb >= 0) run += red[r * 66 + cl];
            }
            if (cur >= 0)
                atomicAdd(&psum[(size_t)cur * 256 + n0 + h * 64 + cl], run);
        }
    }
}

// ---------------- finalize pooled means: write fp16 into A panel rows 0..2047, cols 0..255
__global__ void finalize_kernel(uint16_t* __restrict__ A) {
    int i = blockIdx.x * blockDim.x + threadIdx.x;
    if (i >= N_GRAPHS * HID) return;
    int gidx = i >> 8, c = i & 255;
    float cnt = (float)g_gcnt[gidx];
    float v = g_pool[i] / fmaxf(cnt, 1.f);
    A[(size_t)gidx * 512 + c] = f16_bits(v);
}

// ---------------- launch ----------------
extern "C" void kernel_launch(void* const* d_in, const int* in_sizes, int n_in,
                              void* d_out, int out_size) {
    const float* x   = (const float*)d_in[0];
    const int*   ei  = (const int*)d_in[1];
    const int*   src = ei;
    const int*   dst = ei + N_EDGES;
    const int* batch = (const int*)d_in[2];
    const float* W1l = (const float*)d_in[3];
    const float* b1  = (const float*)d_in[4];
    const float* W1r = (const float*)d_in[5];
    const float* W2l = (const float*)d_in[6];
    const float* b2  = (const float*)d_in[7];
    const float* W2r = (const float*)d_in[8];
    const float* W3  = (const float*)d_in[9];
    const float* b3  = (const float*)d_in[10];
    const float* W4  = (const float*)d_in[11];
    const float* b4  = (const float*)d_in[12];
    float* out = (float*)d_out;

    void *p_pool, *p_A, *p_B1, *p_B2, *p_B3, *p_B4;
    cudaGetSymbolAddress(&p_pool, g_pool);
    cudaGetSymbolAddress(&p_A, g_A);
    cudaGetSymbolAddress(&p_B1, g_B1);
    cudaGetSymbolAddress(&p_B2, g_B2);
    cudaGetSymbolAddress(&p_B3, g_B3);
    cudaGetSymbolAddress(&p_B4, g_B4);
    float* pooled = (float*)p_pool;
    uint16_t* A  = (uint16_t*)p_A;
    uint16_t* B1 = (uint16_t*)p_B1;
    uint16_t* B2 = (uint16_t*)p_B2;
    uint16_t* B3 = (uint16_t*)p_B3;
    uint16_t* B4 = (uint16_t*)p_B4;

    static cudaStream_t s_aux = nullptr;
    static cudaEvent_t ev_fork = nullptr, ev_join = nullptr;
    if (!s_aux) {
        cudaStreamCreateWithFlags(&s_aux, cudaStreamNonBlocking);
        cudaEventCreateWithFlags(&ev_fork, cudaEventDisableTiming);
        cudaEventCreateWithFlags(&ev_join, cudaEventDisableTiming);
    }

    const int TB = 256;
    const dim3 ggrid((N_NODES + 127) / 128, 2);
    const int NSCAN = (N_NODES + 1023) / 1024;

    // ---- fork: weight/x conversions on aux stream ----
    cudaEventRecord(ev_fork, 0);
    cudaStreamWaitEvent(s_aux, ev_fork, 0);
    xconv_kernel<<<(N_NODES * 32 + TB - 1) / TB, TB, 0, s_aux>>>(x, A);
    wconv_kernel<<<(256 * 128 + TB - 1) / TB, TB, 0, s_aux>>>(W1l, 128, 256, 0, B1);
    wconv_kernel<<<(256 * 128 + TB - 1) / TB, TB, 0, s_aux>>>(W1r, 128, 256, 128, B1);
    wconv_kernel<<<(256 * 256 + TB - 1) / TB, TB, 0, s_aux>>>(W2l, 256, 256, 0, B2);
    wconv_kernel<<<(256 * 256 + TB - 1) / TB, TB, 0, s_aux>>>(W2r, 256, 256, 256, B2);
    wconv_kernel<<<(256 * 256 + TB - 1) / TB, TB, 0, s_aux>>>(W3, 256, 256, 0, B3);
    wconv_kernel<<<(128 * 256 + TB - 1) / TB, TB, 0, s_aux>>>(W4, 256, 128, 0, B4);
    cudaEventRecord(ev_join, s_aux);

    // ---- main stream: CSR build + zero pooled sums ----
    zero_kernel<<<(N_GRAPHS * HID + TB - 1) / TB, TB>>>();
    hist_kernel<<<(N_EDGES + TB - 1) / TB, TB>>>(dst, batch);
    scan1_kernel<<<NSCAN, 1024>>>();
    scan2_kernel<<<1, 128>>>(NSCAN);
    scan3_kernel<<<NSCAN, 1024>>>();
    scatter_kernel<<<(N_EDGES + TB - 1) / TB, TB>>>(src, dst);

    // join before agg1 (needs x fp16 panel)
    cudaStreamWaitEvent(0, ev_join, 0);

    // Layer 1: agg over fp16-x panel (cols 128..255) -> cols 0..127; gemm1 K=256
    agg1_kernel<<<(N_NODES * 32 + TB - 1) / TB, TB>>>(A, A);
    hgemm_kernel<<<ggrid, 256>>>(A, B1, 256, b1, A, nullptr, 0, 1, N_NODES,
                                 nullptr, nullptr, 0);

    // Layer 2: agg over fp16-h1 panel (cols 256..511) -> cols 0..255; fused-pool GEMM K=512
    agg2_kernel<<<(N_NODES * 32 + TB - 1) / TB, TB>>>(A, A);
    hgemm_kernel<<<ggrid, 256>>>(A, B2, 512, b2, nullptr, nullptr, 0, 1, N_NODES,
                                 batch, pooled, 1);

    // pooled means (fp16 into A panel rows 0..2047, cols 0..255)
    finalize_kernel<<<(N_GRAPHS * HID + TB - 1) / TB, TB>>>(A);

    // MLP head on fp16 HMMA path
    {
        dim3 grid((N_GRAPHS + 127) / 128, 2);
        hgemm_kernel<<<grid, 256>>>(A, B3, 256, b3, A, nullptr, 0, 1, N_GRAPHS,
                                    nullptr, nullptr, 0);   // hidden fp16 -> cols 256..511
    }
    {
        dim3 grid((N_GRAPHS + 127) / 128, 1);
        hgemm_kernel<<<grid, 256>>>(A + 256, B4, 256, b4, nullptr, out, 128, 0, N_GRAPHS,
                                    nullptr, nullptr, 0);   // fp32 out [2048,128], no relu
    }
}

// round 16
// speedup vs baseline: 2.8145x; 1.3382x over previous
#include <cuda_runtime.h>
#include <cuda_fp16.h>
#include <cstdint>

#define N_NODES  100000
#define N_EDGES  1600000
#define IN_CH    128
#define HID      256
#define OUT_CH   128
#define N_GRAPHS 2048

// ---------------- scratch (device globals: no allocation allowed) ----------------
__device__ int   g_deg[N_NODES];
__device__ int   g_fill[N_NODES];
__device__ int   g_rowptr[N_NODES + 1];
__device__ int   g_col[N_EDGES];
__device__ int   g_part[128];
__device__ int   g_part2[128];
__device__ int   g_gcnt[N_GRAPHS];
__device__ uint16_t g_A [(size_t)N_NODES * 512];     // fp16 A panel (stride 512)
__device__ uint16_t g_B1[256 * 512];                 // fp16 B panels (n-major, stride 512)
__device__ uint16_t g_B2[256 * 512];
__device__ uint16_t g_B3[256 * 512];
__device__ uint16_t g_B4[256 * 512];                 // rows 128..255 stay zero
__device__ float g_pool[N_GRAPHS * HID];

// ---------------- helpers ----------------
__device__ __forceinline__ uint16_t f16_bits(float v) {
    __half h = __float2half_rn(v);
    return *(uint16_t*)&h;
}
__device__ __forceinline__ uint32_t smem_u32(const void* p) {
    uint32_t a;
    asm("{ .reg .u64 t; cvta.to.shared.u64 t, %1; cvt.u32.u64 %0, t; }" : "=r"(a) : "l"(p));
    return a;
}

// ---------------- CSR build + zero ----------------
__global__ void zero_kernel() {
    int i = blockIdx.x * blockDim.x + threadIdx.x;
    if (i < N_NODES) { g_deg[i] = 0; g_fill[i] = 0; }
    if (i < N_GRAPHS * HID) g_pool[i] = 0.f;
    if (i < N_GRAPHS) g_gcnt[i] = 0;
}
__global__ void hist_kernel(const int* __restrict__ dst, const int* __restrict__ batch) {
    int e = blockIdx.x * blockDim.x + threadIdx.x;
    if (e < N_EDGES) atomicAdd(&g_deg[dst[e]], 1);
    if (e < N_NODES) atomicAdd(&g_gcnt[batch[e]], 1);
}
__global__ void scan1_kernel() {
    __shared__ int sh[1024];
    int t = threadIdx.x;
    int i = blockIdx.x * 1024 + t;
    sh[t] = (i < N_NODES) ? g_deg[i] : 0;
    __syncthreads();
    for (int off = 512; off > 0; off >>= 1) {
        if (t < off) sh[t] += sh[t + off];
        __syncthreads();
    }
    if (t == 0) g_part[blockIdx.x] = sh[0];
}
__global__ void scan2_kernel(int nparts) {
    __shared__ int sh[128];
    int t = threadIdx.x;
    int v = (t < nparts) ? g_part[t] : 0;
    sh[t] = v;
    __syncthreads();
    for (int off = 1; off < 128; off <<= 1) {
        int nv = (t >= off) ? sh[t - off] : 0;
        __syncthreads();
        sh[t] += nv;
        __syncthreads();
    }
    if (t < nparts) g_part2[t] = sh[t] - v;
    if (t == 0) g_rowptr[N_NODES] = N_EDGES;
}
__global__ void scan3_kernel() {
    __shared__ int sh[1024];
    int t = threadIdx.x;
    int i = blockIdx.x * 1024 + t;
    int v = (i < N_NODES) ? g_deg[i] : 0;
    sh[t] = v;
    __syncthreads();
    for (int off = 1; off < 1024; off <<= 1) {
        int nv = (t >= off) ? sh[t - off] : 0;
        __syncthreads();
        sh[t] += nv;
        __syncthreads();
    }
    if (i < N_NODES) g_rowptr[i] = sh[t] - v + g_part2[blockIdx.x];
}
__global__ void scatter_kernel(const int* __restrict__ src, const int* __restrict__ dst) {
    int e = blockIdx.x * blockDim.x + threadIdx.x;
    if (e >= N_EDGES) return;
    int d = dst[e];
    int p = g_rowptr[d] + atomicAdd(&g_fill[d], 1);
    g_col[p] = src[e];
}

// ---------------- fp16 writers / readers ----------------
__device__ __forceinline__ void h_store4(uint16_t* A, size_t base,
                                         float v0, float v1, float v2, float v3) {
    uint16_t h0 = f16_bits(v0), h1 = f16_bits(v1), h2 = f16_bits(v2), h3 = f16_bits(v3);
    *(uint2*)(A + base) = make_uint2((uint32_t)h0 | ((uint32_t)h1 << 16),
                                     (uint32_t)h2 | ((uint32_t)h3 << 16));
}
__device__ __forceinline__ void add4h(float* acc, uint2 h) {
    const uint32_t* hp = (const uint32_t*)&h;
#pragma unroll
    for (int i = 0; i < 2; i++) {
        __half2 hb = *(__half2*)&hp[i];
        float2 hf = __half22float2(hb);
        acc[i * 2]     += hf.x;
        acc[i * 2 + 1] += hf.y;
    }
}
__device__ __forceinline__ void add8h(float* acc, uint4 h) {
    const uint32_t* hp = (const uint32_t*)&h;
#pragma unroll
    for (int i = 0; i < 4; i++) {
        __half2 hb = *(__half2*)&hp[i];
        float2 hf = __half22float2(hb);
        acc[i * 2]     += hf.x;
        acc[i * 2 + 1] += hf.y;
    }
}

// layer-1 mean aggregation: gathers fp16 x (panel cols 128..255), 8-way edge unroll
__global__ void agg1_kernel(const uint16_t* __restrict__ Ap, uint16_t* __restrict__ A) {
    int w = (blockIdx.x * blockDim.x + threadIdx.x) >> 5;
    int lane = threadIdx.x & 31;
    if (w >= N_NODES) return;
    int beg = g_rowptr[w], end = g_rowptr[w + 1];
    float acc[4];
#pragma unroll
    for (int i = 0; i < 4; i++) acc[i] = 0.f;
    int j = beg;
    for (; j + 7 < end; j += 8) {
        uint2 h[8];
#pragma unroll
        for (int q = 0; q < 8; q++)
            h[q] = *(const uint2*)(Ap + (size_t)g_col[j + q] * 512 + 128 + lane * 4);
#pragma unroll
        for (int q = 0; q < 8; q++) add4h(acc, h[q]);
    }
    for (; j < end; j++) {
        uint2 h0 = *(const uint2*)(Ap + (size_t)g_col[j] * 512 + 128 + lane * 4);
        add4h(acc, h0);
    }
    float inv = (end > beg) ? 1.f / (float)(end - beg) : 0.f;
    h_store4(A, (size_t)w * 512 + (size_t)lane * 4,
             acc[0] * inv, acc[1] * inv, acc[2] * inv, acc[3] * inv);
}

// layer-2 mean aggregation: gathers fp16 h1 (panel cols 256..511), 8-way edge unroll
__global__ void agg2_kernel(const uint16_t* __restrict__ Ap, uint16_t* __restrict__ A) {
    int w = (blockIdx.x * blockDim.x + threadIdx.x) >> 5;
    int lane = threadIdx.x & 31;
    if (w >= N_NODES) return;
    int beg = g_rowptr[w], end = g_rowptr[w + 1];
    float acc[8];
#pragma unroll
    for (int i = 0; i < 8; i++) acc[i] = 0.f;
    int j = beg;
    for (; j + 7 < end; j += 8) {
        uint4 h[8];
#pragma unroll
        for (int q = 0; q < 8; q++)
            h[q] = *(const uint4*)(Ap + (size_t)g_col[j + q] * 512 + 256 + lane * 8);
#pragma unroll
        for (int q = 0; q < 8; q++) add8h(acc, h[q]);
    }
    for (; j < end; j++) {
        uint4 h0 = *(const uint4*)(Ap + (size_t)g_col[j] * 512 + 256 + lane * 8);
        add8h(acc, h0);
    }
    float inv = (end > beg) ? 1.f / (float)(end - beg) : 0.f;
    size_t base = (size_t)w * 512 + (size_t)lane * 8;
    h_store4(A, base,     acc[0] * inv, acc[1] * inv, acc[2] * inv, acc[3] * inv);
    h_store4(A, base + 4, acc[4] * inv, acc[5] * inv, acc[6] * inv, acc[7] * inv);
}

// convert x (fp32 [N,128]) into A panel cols 128..255
__global__ void xconv_kernel(const float* __restrict__ x, uint16_t* __restrict__ A) {
    int idx = blockIdx.x * blockDim.x + threadIdx.x;
    if (idx >= N_NODES * 32) return;
    int row = idx >> 5, q = idx & 31;
    float4 v = ((const float4*)x)[idx];
    h_store4(A, (size_t)row * 512 + 128 + (size_t)q * 4, v.x, v.y, v.z, v.w);
}

// transpose + convert weight W[Kw,Nout] into B panel rows n<Nout
__global__ void wconv_kernel(const float* __restrict__ W, int Kw, int Nout, int cofs,
                             uint16_t* __restrict__ B) {
    int idx = blockIdx.x * blockDim.x + threadIdx.x;
    if (idx >= Nout * Kw) return;
    int n = idx / Kw, k = idx - n * Kw;
    B[(size_t)n * 512 + cofs + k] = f16_bits(W[(size_t)k * Nout + n]);
}

// ---------------- single-pass fp16 HMMA GEMM, K-chunk = 64 ----------------
#define LDB_S 72    // smem row stride in fp16 elems (144B): ldmatrix conflict-free

__device__ __forceinline__ void mma_f16(float* c, const uint32_t* a, const uint32_t* b) {
    asm volatile(
        "mma.sync.aligned.m16n8k16.row.col.f32.f16.f16.f32 "
        "{%0,%1,%2,%3}, {%4,%5,%6,%7}, {%8,%9}, {%0,%1,%2,%3};"
        : "+f"(c[0]), "+f"(c[1]), "+f"(c[2]), "+f"(c[3])
        : "r"(a[0]), "r"(a[1]), "r"(a[2]), "r"(a[3]), "r"(b[0]), "r"(b[1]));
}
__device__ __forceinline__ void ldsm_x4(uint32_t* r, uint32_t addr) {
    asm volatile("ldmatrix.sync.aligned.m8n8.x4.shared.b16 {%0,%1,%2,%3}, [%4];"
                 : "=r"(r[0]), "=r"(r[1]), "=r"(r[2]), "=r"(r[3]) : "r"(addr));
}

__global__ __launch_bounds__(256) void hgemm_kernel(
    const uint16_t* __restrict__ A, const uint16_t* __restrict__ B,
    int K, const float* __restrict__ bias,
    uint16_t* __restrict__ oA,            // fp16 panel out (cols 256..511) or nullptr
    float* __restrict__ Cf, int ldc,      // fp32 out or nullptr
    int do_relu, int M,
    const int* __restrict__ batchp, float* __restrict__ psum, int fuse_pool)
{
    __shared__ __align__(16) uint8_t smraw[36864];   // As 18432 + Bs 18432 (K=64 chunk)
    uint16_t* As = (uint16_t*)(smraw);
    uint16_t* Bs = (uint16_t*)(smraw + 18432);

    const int tid = threadIdx.x;
    const int lane = tid & 31, wid = tid >> 5;
    const int wm = wid & 3, wn = wid >> 2;
    const int g = lane >> 2, th = lane & 3;
    const int row0 = blockIdx.x * 128;
    const int n0 = blockIdx.y * 128;

    const uint32_t sA = smem_u32(smraw);
    const uint32_t sB = sA + 18432;

    const int nch = K >> 6;   // K is a multiple of 64 here (256 or 512)

    float acc[2][8][4];
#pragma unroll
    for (int mt = 0; mt < 2; mt++)
#pragma unroll
        for (int nt = 0; nt < 8; nt++)
#pragma unroll
            for (int r = 0; r < 4; r++) acc[mt][nt][r] = 0.f;

    const int lt = lane >> 3, lr = lane & 7;

    // loader: 128 rows x 8 16B-units per array; unit u = tid + i*256, i<4
    uint4 ra[4], rb[4];
    {
#pragma unroll
        for (int i = 0; i < 4; i++) {
            int u = tid + i * 256;
            int r = u >> 3, q = u & 7;
            int ga = row0 + r;
            ra[i] = (ga < M) ? *(const uint4*)(A + (size_t)ga * 512 + q * 8)
                             : make_uint4(0, 0, 0, 0);
            rb[i] = *(const uint4*)(B + (size_t)(n0 + r) * 512 + q * 8);
        }
    }

#pragma unroll 1
    for (int c = 0; c < nch; c++) {
#pragma unroll
        for (int i = 0; i < 4; i++) {
            int u = tid + i * 256;
            int r = u >> 3, q = u & 7;
            int so = r * LDB_S + q * 8;
            *(uint4*)&As[so] = ra[i];
            *(uint4*)&Bs[so] = rb[i];
        }
        __syncthreads();

        if (c + 1 < nch) {
            int kb = (c + 1) * 64;
#pragma unroll
            for (int i = 0; i < 4; i++) {
                int u = tid + i * 256;
                int r = u >> 3, q = u & 7;
                int ga = row0 + r;
                ra[i] = (ga < M) ? *(const uint4*)(A + (size_t)ga * 512 + kb + q * 8)
                                 : make_uint4(0, 0, 0, 0);
                rb[i] = *(const uint4*)(B + (size_t)(n0 + r) * 512 + kb + q * 8);
            }
        }

#pragma unroll
        for (int step = 0; step < 4; step++) {
            const int k0 = step * 16;
            uint32_t aoff[2];
#pragma unroll
            for (int mt = 0; mt < 2; mt++) {
                int ar = wm * 32 + mt * 16 + (lt & 1) * 8 + lr;
                int ak = k0 + (lt >> 1) * 8;
                aoff[mt] = (uint32_t)(ar * LDB_S + ak) * 2;
            }
            uint32_t boff[4];
#pragma unroll
            for (int ntp = 0; ntp < 4; ntp++) {
                int nr = wn * 64 + ntp * 16 + (lt >> 1) * 8 + lr;
                int nk = k0 + (lt & 1) * 8;
                boff[ntp] = (uint32_t)(nr * LDB_S + nk) * 2;
            }

            uint32_t ah[2][4], bh[4][4];
#pragma unroll
            for (int mt = 0; mt < 2; mt++) ldsm_x4(ah[mt], sA + aoff[mt]);
#pragma unroll
            for (int ntp = 0; ntp < 4; ntp++) ldsm_x4(bh[ntp], sB + boff[ntp]);
#pragma unroll
            for (int mt = 0; mt < 2; mt++)
#pragma unroll
                for (int nt = 0; nt < 8; nt++)
                    mma_f16(acc[mt][nt], ah[mt], &bh[nt >> 1][(nt & 1) * 2]);
        }
        __syncthreads();
    }

    if (!fuse_pool) {
#pragma unroll
        for (int mt = 0; mt < 2; mt++) {
            int rbase = row0 + wm * 32 + mt * 16 + g;
#pragma unroll
            for (int nt = 0; nt < 8; nt++) {
                int col = n0 + wn * 64 + nt * 8 + th * 2;
                float bx = bias[col], by = bias[col + 1];
                float2 v0 = make_float2(acc[mt][nt][0] + bx, acc[mt][nt][1] + by);
                float2 v1 = make_float2(acc[mt][nt][2] + bx, acc[mt][nt][3] + by);
                if (do_relu) {
                    v0.x = fmaxf(v0.x, 0.f); v0.y = fmaxf(v0.y, 0.f);
                    v1.x = fmaxf(v1.x, 0.f); v1.y = fmaxf(v1.y, 0.f);
                }
                if (rbase < M) {
                    if (oA) {
                        uint16_t h0 = f16_bits(v0.x), h1 = f16_bits(v0.y);
                        *(uint32_t*)(oA + (size_t)rbase * 512 + 256 + col) =
                            (uint32_t)h0 | ((uint32_t)h1 << 16);
                    }
                    if (Cf) *(float2*)(Cf + (size_t)rbase * ldc + col) = v0;
                }
                if (rbase + 8 < M) {
                    if (oA) {
                        uint16_t h0 = f16_bits(v1.x), h1 = f16_bits(v1.y);
                        *(uint32_t*)(oA + (size_t)(rbase + 8) * 512 + 256 + col) =
                            (uint32_t)h0 | ((uint32_t)h1 << 16);
                    }
                    if (Cf) *(float2*)(Cf + (size_t)(rbase + 8) * ldc + col) = v1;
                }
            }
        }
    } else {
        float* red = (float*)smraw;              // [128][66] = 33792B <= 36864
        __shared__ int sbat[128];
#pragma unroll 1
        for (int h = 0; h < 2; h++) {
            __syncthreads();
            if (tid < 128) sbat[tid] = (row0 + tid < M) ? batchp[row0 + tid] : -1;
            if (wn == h) {
#pragma unroll
                for (int mt = 0; mt < 2; mt++) {
                    int rl = wm * 32 + mt * 16 + g;
#pragma unroll
                    for (int nt = 0; nt < 8; nt++) {
                        int cl = nt * 8 + th * 2;
                        int colg = n0 + h * 64 + cl;
                        float bx = bias[colg], by = bias[colg + 1];
                        red[rl * 66 + cl]       = fmaxf(acc[mt][nt][0] + bx, 0.f);
                        red[rl * 66 + cl + 1]   = fmaxf(acc[mt][nt][1] + by, 0.f);
                        red[(rl + 8) * 66 + cl]     = fmaxf(acc[mt][nt][2] + bx, 0.f);
                        red[(rl + 8) * 66 + cl + 1] = fmaxf(acc[mt][nt][3] + by, 0.f);
                    }
                }
            }
            __syncthreads();
            int cl = tid & 63, rh = tid >> 6;
            float run = 0.f; int cur = -1;
#pragma unroll 1
            for (int r = rh * 32; r < rh * 32 + 32; r++) {
                int gb = sbat[r];
                if (gb != cur) {
                    if (cur >= 0)
                        atomicAdd(&psum[(size_t)cur * 256 + n0 + h * 64 + cl], run);
                    run = 0.f; cur = gb;
                }
                if (gb >= 0) run += red[r * 66 + cl];
            }
            if (cur >= 0)
                atomicAdd(&psum[(size_t)cur * 256 + n0 + h * 64 + cl], run);
        }
    }
}

// ---------------- finalize pooled means: write fp16 into A panel rows 0..2047, cols 0..255
__global__ void finalize_kernel(uint16_t* __restrict__ A) {
    int i = blockIdx.x * blockDim.x + threadIdx.x;
    if (i >= N_GRAPHS * HID) return;
    int gidx = i >> 8, c = i & 255;
    float cnt = (float)g_gcnt[gidx];
    float v = g_pool[i] / fmaxf(cnt, 1.f);
    A[(size_t)gidx * 512 + c] = f16_bits(v);
}

// ---------------- launch ----------------
extern "C" void kernel_launch(void* const* d_in, const int* in_sizes, int n_in,
                              void* d_out, int out_size) {
    const float* x   = (const float*)d_in[0];
    const int*   ei  = (const int*)d_in[1];
    const int*   src = ei;
    const int*   dst = ei + N_EDGES;
    const int* batch = (const int*)d_in[2];
    const float* W1l = (const float*)d_in[3];
    const float* b1  = (const float*)d_in[4];
    const float* W1r = (const float*)d_in[5];
    const float* W2l = (const float*)d_in[6];
    const float* b2  = (const float*)d_in[7];
    const float* W2r = (const float*)d_in[8];
    const float* W3  = (const float*)d_in[9];
    const float* b3  = (const float*)d_in[10];
    const float* W4  = (const float*)d_in[11];
    const float* b4  = (const float*)d_in[12];
    float* out = (float*)d_out;

    void *p_pool, *p_A, *p_B1, *p_B2, *p_B3, *p_B4;
    cudaGetSymbolAddress(&p_pool, g_pool);
    cudaGetSymbolAddress(&p_A, g_A);
    cudaGetSymbolAddress(&p_B1, g_B1);
    cudaGetSymbolAddress(&p_B2, g_B2);
    cudaGetSymbolAddress(&p_B3, g_B3);
    cudaGetSymbolAddress(&p_B4, g_B4);
    float* pooled = (float*)p_pool;
    uint16_t* A  = (uint16_t*)p_A;
    uint16_t* B1 = (uint16_t*)p_B1;
    uint16_t* B2 = (uint16_t*)p_B2;
    uint16_t* B3 = (uint16_t*)p_B3;
    uint16_t* B4 = (uint16_t*)p_B4;

    static cudaStream_t s_aux = nullptr;
    static cudaEvent_t ev_fork = nullptr, ev_join = nullptr;
    if (!s_aux) {
        cudaStreamCreateWithFlags(&s_aux, cudaStreamNonBlocking);
        cudaEventCreateWithFlags(&ev_fork, cudaEventDisableTiming);
        cudaEventCreateWithFlags(&ev_join, cudaEventDisableTiming);
    }

    const int TB = 256;
    const dim3 ggrid((N_NODES + 127) / 128, 2);
    const int NSCAN = (N_NODES + 1023) / 1024;

    // ---- fork: weight/x conversions on aux stream ----
    cudaEventRecord(ev_fork, 0);
    cudaStreamWaitEvent(s_aux, ev_fork, 0);
    xconv_kernel<<<(N_NODES * 32 + TB - 1) / TB, TB, 0, s_aux>>>(x, A);
    wconv_kernel<<<(256 * 128 + TB - 1) / TB, TB, 0, s_aux>>>(W1l, 128, 256, 0, B1);
    wconv_kernel<<<(256 * 128 + TB - 1) / TB, TB, 0, s_aux>>>(W1r, 128, 256, 128, B1);
    wconv_kernel<<<(256 * 256 + TB - 1) / TB, TB, 0, s_aux>>>(W2l, 256, 256, 0, B2);
    wconv_kernel<<<(256 * 256 + TB - 1) / TB, TB, 0, s_aux>>>(W2r, 256, 256, 256, B2);
    wconv_kernel<<<(256 * 256 + TB - 1) / TB, TB, 0, s_aux>>>(W3, 256, 256, 0, B3);
    wconv_kernel<<<(128 * 256 + TB - 1) / TB, TB, 0, s_aux>>>(W4, 256, 128, 0, B4);
    cudaEventRecord(ev_join, s_aux);

    // ---- main stream: CSR build + zero pooled sums ----
    zero_kernel<<<(N_GRAPHS * HID + TB - 1) / TB, TB>>>();
    hist_kernel<<<(N_EDGES + TB - 1) / TB, TB>>>(dst, batch);
    scan1_kernel<<<NSCAN, 1024>>>();
    scan2_kernel<<<1, 128>>>(NSCAN);
    scan3_kernel<<<NSCAN, 1024>>>();
    scatter_kernel<<<(N_EDGES + TB - 1) / TB, TB>>>(src, dst);

    // join before agg1 (needs x fp16 panel)
    cudaStreamWaitEvent(0, ev_join, 0);

    // Layer 1: agg over fp16-x panel (cols 128..255) -> cols 0..127; gemm1 K=256
    agg1_kernel<<<(N_NODES * 32 + TB - 1) / TB, TB>>>(A, A);
    hgemm_kernel<<<ggrid, 256>>>(A, B1, 256, b1, A, nullptr, 0, 1, N_NODES,
                                 nullptr, nullptr, 0);

    // Layer 2: agg over fp16-h1 panel (cols 256..511) -> cols 0..255; fused-pool GEMM K=512
    agg2_kernel<<<(N_NODES * 32 + TB - 1) / TB, TB>>>(A, A);
    hgemm_kernel<<<ggrid, 256>>>(A, B2, 512, b2, nullptr, nullptr, 0, 1, N_NODES,
                                 batch, pooled, 1);

    // pooled means (fp16 into A panel rows 0..2047, cols 0..255)
    finalize_kernel<<<(N_GRAPHS * HID + TB - 1) / TB, TB>>>(A);

    // MLP head on fp16 HMMA path
    {
        dim3 grid((N_GRAPHS + 127) / 128, 2);
        hgemm_kernel<<<grid, 256>>>(A, B3, 256, b3, A, nullptr, 0, 1, N_GRAPHS,
                                    nullptr, nullptr, 0);   // hidden fp16 -> cols 256..511
    }
    {
        dim3 grid((N_GRAPHS + 127) / 128, 1);
        hgemm_kernel<<<grid, 256>>>(A + 256, B4, 256, b4, nullptr, out, 128, 0, N_GRAPHS,
                                    nullptr, nullptr, 0);   // fp32 out [2048,128], no relu
    }
}